// round 3
// baseline (speedup 1.0000x reference)
#include <cuda_runtime.h>
#include <cuda_bf16.h>
#include <math.h>

// ---------------------------------------------------------------------------
// Problem constants
// ---------------------------------------------------------------------------
#define BATCH   2
#define SEQ     2048
#define EMBED   3584
#define NH      16
#define NKV     8
#define HDIM    256
#define MROWS   (BATCH*SEQ)          // 4096
#define QCOLS   (NH*HDIM)            // 4096
#define KCOLS   (NKV*HDIM)           // 2048
#define WINDOW  1024

// ---------------------------------------------------------------------------
// Scratch (static device allocations; harness forbids cudaMalloc)
// ---------------------------------------------------------------------------
__device__ float g_Q[(size_t)MROWS*QCOLS];    // 64 MB
__device__ float g_K[(size_t)MROWS*KCOLS];    // 32 MB
__device__ float g_V[(size_t)MROWS*KCOLS];    // 32 MB
__device__ float g_Ctx[(size_t)MROWS*QCOLS];  // 64 MB
__device__ float g_cos[SEQ*(HDIM/2)];         // 1 MB
__device__ float g_sin[SEQ*(HDIM/2)];         // 1 MB

// ---------------------------------------------------------------------------
// f32x2 packed math helpers (Blackwell FFMA2 — only reachable via PTX)
// ---------------------------------------------------------------------------
__device__ __forceinline__ unsigned long long pk2(float lo, float hi) {
    unsigned long long r;
    asm("mov.b64 %0, {%1, %2};" : "=l"(r) : "f"(lo), "f"(hi));
    return r;
}
__device__ __forceinline__ float2 upk2(unsigned long long v) {
    float2 r;
    asm("mov.b64 {%0, %1}, %2;" : "=f"(r.x), "=f"(r.y) : "l"(v));
    return r;
}
__device__ __forceinline__ unsigned long long fma2(unsigned long long a,
                                                   unsigned long long b,
                                                   unsigned long long c) {
    unsigned long long d;
    asm("fma.rn.f32x2 %0, %1, %2, %3;" : "=l"(d) : "l"(a), "l"(b), "l"(c));
    return d;
}
__device__ __forceinline__ unsigned long long mul2(unsigned long long a,
                                                   unsigned long long b) {
    unsigned long long d;
    asm("mul.rn.f32x2 %0, %1, %2;" : "=l"(d) : "l"(a), "l"(b));
    return d;
}

// ---------------------------------------------------------------------------
// SGEMM: C[M,N] = A[M,K] @ B[K,N], all row-major fp32, M%128==0, N%128==0, K%8==0
// 128x128x8 blocking, 256 threads, 8x8 microtile as 2x2 of 4x4 (conflict-free
// float4 smem reads), accumulators in packed f32x2.
// ---------------------------------------------------------------------------
#define BM 128
#define BN 128
#define BKK 8

__global__ void __launch_bounds__(256) sgemm_kernel(
    const float* __restrict__ A, const float* __restrict__ B,
    float* __restrict__ C, int M, int N, int K)
{
    __shared__ float As[BKK][BM];
    __shared__ float Bs[BKK][BN];

    const int tid = threadIdx.x;
    const int tr = tid >> 4;         // 0..15 (row group)
    const int tc = tid & 15;         // 0..15 (col group)

    const int aRow = tid >> 1;       // 0..127
    const int aCol = (tid & 1) * 4;  // 0 or 4
    const int bRow = tid >> 5;       // 0..7
    const int bCol = (tid & 31) * 4; // 0..124

    const float* Ap = A + (size_t)(blockIdx.y * BM) * K;
    const float* Bp = B + (size_t)(blockIdx.x * BN);

    unsigned long long c2[2][2][4][2];
    const unsigned long long z = pk2(0.f, 0.f);
#pragma unroll
    for (int ih = 0; ih < 2; ih++)
#pragma unroll
        for (int jh = 0; jh < 2; jh++)
#pragma unroll
            for (int i = 0; i < 4; i++) { c2[ih][jh][i][0] = z; c2[ih][jh][i][1] = z; }

    for (int k0 = 0; k0 < K; k0 += BKK) {
        float4 av = *(const float4*)(Ap + (size_t)aRow * K + k0 + aCol);
        float4 bv = *(const float4*)(Bp + (size_t)(k0 + bRow) * N + bCol);
        __syncthreads();
        As[aCol + 0][aRow] = av.x;
        As[aCol + 1][aRow] = av.y;
        As[aCol + 2][aRow] = av.z;
        As[aCol + 3][aRow] = av.w;
        *(float4*)&Bs[bRow][bCol] = bv;
        __syncthreads();

#pragma unroll
        for (int kk = 0; kk < BKK; kk++) {
            float4 a0 = *(const float4*)&As[kk][tr * 4];
            float4 a1 = *(const float4*)&As[kk][64 + tr * 4];
            float4 b0 = *(const float4*)&Bs[kk][tc * 4];
            float4 b1 = *(const float4*)&Bs[kk][64 + tc * 4];
            unsigned long long bp[2][2];
            bp[0][0] = pk2(b0.x, b0.y); bp[0][1] = pk2(b0.z, b0.w);
            bp[1][0] = pk2(b1.x, b1.y); bp[1][1] = pk2(b1.z, b1.w);
            float aa[2][4] = {{a0.x, a0.y, a0.z, a0.w}, {a1.x, a1.y, a1.z, a1.w}};
#pragma unroll
            for (int ih = 0; ih < 2; ih++)
#pragma unroll
                for (int i = 0; i < 4; i++) {
                    unsigned long long ap = pk2(aa[ih][i], aa[ih][i]);
#pragma unroll
                    for (int jh = 0; jh < 2; jh++) {
                        c2[ih][jh][i][0] = fma2(ap, bp[jh][0], c2[ih][jh][i][0]);
                        c2[ih][jh][i][1] = fma2(ap, bp[jh][1], c2[ih][jh][i][1]);
                    }
                }
        }
    }

    const size_t rowBase = (size_t)blockIdx.y * BM;
    const size_t colBase = (size_t)blockIdx.x * BN;
#pragma unroll
    for (int ih = 0; ih < 2; ih++)
#pragma unroll
        for (int i = 0; i < 4; i++) {
            size_t row = rowBase + ih * 64 + tr * 4 + i;
            float* crow = C + row * N + colBase;
#pragma unroll
            for (int jh = 0; jh < 2; jh++) {
                float2 lo = upk2(c2[ih][jh][i][0]);
                float2 hi = upk2(c2[ih][jh][i][1]);
                float4 o = make_float4(lo.x, lo.y, hi.x, hi.y);
                *(float4*)(crow + jh * 64 + tc * 4) = o;
            }
        }
}

// ---------------------------------------------------------------------------
// RoPE tables (double precision; ~1 ulp of true values)
// ---------------------------------------------------------------------------
__global__ void rope_tables_kernel()
{
    int idx = blockIdx.x * 256 + threadIdx.x;
    if (idx >= SEQ * (HDIM / 2)) return;
    int i = idx & 127;
    int pos = idx >> 7;
    double invf = pow(10000.0, -(double)(2 * i) / (double)HDIM);
    double ang = (double)pos * invf;
    g_cos[idx] = (float)cos(ang);
    g_sin[idx] = (float)sin(ang);
}

// ---------------------------------------------------------------------------
// RoPE apply (in place), X is [MROWS, heads*HDIM]
// ---------------------------------------------------------------------------
__global__ void rope_apply_kernel(float* __restrict__ X, int heads)
{
    int idx = blockIdx.x * 256 + threadIdx.x;
    int total = MROWS * heads * (HDIM / 2);
    if (idx >= total) return;
    int i = idx & 127;          // dim pair index (fastest -> coalesced)
    int t = idx >> 7;
    int h = t % heads;
    int m = t / heads;
    int pos = m & (SEQ - 1);
    float c = g_cos[pos * 128 + i];
    float s = g_sin[pos * 128 + i];
    float* p = X + (size_t)m * (heads * HDIM) + h * HDIM + i;
    float x1 = p[0];
    float x2 = p[128];
    p[0]   = x1 * c - x2 * s;
    p[128] = x2 * c + x1 * s;
}

// ---------------------------------------------------------------------------
// Fused flash attention with tanh soft-cap and symmetric window mask.
// Block = (q-tile of 64) x (b,h). 256 threads. All fp32, f32x2 FMAs.
//   S-phase: thread owns rows {tr*4+i}, cols {tc+16j}      (4x4)
//   PV-phase: thread owns rows {tr*4+i}, cols {tc*4+64jj}  (4x16)
// ---------------------------------------------------------------------------
#define AQ 64
#define AK 64
#define QSTR 260          // padded: row stride 1040B == 16 mod 128 -> bank-spread
#define KSTR 260
#define VSTR 256
#define PSTR 68
#define ATTN_SMEM_FLOATS (AQ*QSTR + AK*KSTR + AK*VSTR + AQ*PSTR)
#define ATTN_SMEM_BYTES  (ATTN_SMEM_FLOATS * 4)

__global__ void __launch_bounds__(256) attn_kernel(
    const float* __restrict__ Q, const float* __restrict__ K,
    const float* __restrict__ V, float* __restrict__ Ctx)
{
    extern __shared__ float sm[];
    float* Qs = sm;                       // [64][260]
    float* Ks = Qs + AQ * QSTR;           // [64][260]
    float* Vs = Ks + AK * KSTR;           // [64][256]
    float* Ps = Vs + AK * VSTR;           // [64][68]

    const int bh = blockIdx.y;            // b*16 + h
    const int b  = bh >> 4;
    const int h  = bh & 15;
    const int kvh = h >> 1;               // GQA: repeat factor 2
    const int q0 = blockIdx.x * AQ;

    const int tid = threadIdx.x;
    const int tr = tid >> 4;              // 0..15
    const int tc = tid & 15;              // 0..15

    const float* Qg = Q + ((size_t)(b * SEQ + q0)) * QCOLS + h * HDIM;
    const float* Kg = K + ((size_t)(b * SEQ)) * KCOLS + kvh * HDIM;
    const float* Vg = V + ((size_t)(b * SEQ)) * KCOLS + kvh * HDIM;

    // load Q tile (64 x 256)
#pragma unroll
    for (int t = 0; t < 16; t++) {
        int idx = tid + t * 256;
        int r = idx >> 6, c4 = idx & 63;
        float4 v = *(const float4*)(Qg + (size_t)r * QCOLS + c4 * 4);
        *(float4*)(Qs + r * QSTR + c4 * 4) = v;
    }

    unsigned long long o2[4][4][2];
    const unsigned long long z = pk2(0.f, 0.f);
#pragma unroll
    for (int i = 0; i < 4; i++)
#pragma unroll
        for (int jj = 0; jj < 4; jj++) { o2[i][jj][0] = z; o2[i][jj][1] = z; }

    float mrow[4] = {-1e30f, -1e30f, -1e30f, -1e30f};
    float lrow[4] = {0.f, 0.f, 0.f, 0.f};

    int klo = q0 - WINDOW;            if (klo < 0) klo = 0;
    int khi = q0 + AQ + WINDOW;       if (khi > SEQ) khi = SEQ;   // exclusive
    const int kt0 = klo >> 6;
    const int kt1 = (khi >> 6) - 1;   // tile-aligned: 1024 and 64 | q0

    for (int kt = kt0; kt <= kt1; kt++) {
        __syncthreads();  // previous PV done before overwriting K/V
        const int kbase = kt * AK;
#pragma unroll
        for (int t = 0; t < 16; t++) {
            int idx = tid + t * 256;
            int r = idx >> 6, c4 = idx & 63;
            float4 kv = *(const float4*)(Kg + (size_t)(kbase + r) * KCOLS + c4 * 4);
            *(float4*)(Ks + r * KSTR + c4 * 4) = kv;
            float4 vv = *(const float4*)(Vg + (size_t)(kbase + r) * KCOLS + c4 * 4);
            *(float4*)(Vs + r * VSTR + c4 * 4) = vv;
        }
        __syncthreads();

        // ---- S = Q K^T over d=0..255 (f32x2 pairs along d) ----
        unsigned long long s2[4][4];
#pragma unroll
        for (int i = 0; i < 4; i++)
#pragma unroll
            for (int j = 0; j < 4; j++) s2[i][j] = z;

#pragma unroll 4
        for (int d = 0; d < HDIM; d += 4) {
            unsigned long long qp0[4], qp1[4];
#pragma unroll
            for (int i = 0; i < 4; i++) {
                float4 q4 = *(const float4*)(Qs + (tr * 4 + i) * QSTR + d);
                qp0[i] = pk2(q4.x, q4.y);
                qp1[i] = pk2(q4.z, q4.w);
            }
#pragma unroll
            for (int j = 0; j < 4; j++) {
                float4 k4 = *(const float4*)(Ks + (tc + 16 * j) * KSTR + d);
                unsigned long long kp0 = pk2(k4.x, k4.y);
                unsigned long long kp1 = pk2(k4.z, k4.w);
#pragma unroll
                for (int i = 0; i < 4; i++) {
                    s2[i][j] = fma2(qp0[i], kp0, s2[i][j]);
                    s2[i][j] = fma2(qp1[i], kp1, s2[i][j]);
                }
            }
        }

        // ---- soft-cap logits, window mask, online softmax ----
        float scl[4];
#pragma unroll
        for (int i = 0; i < 4; i++) {
            const int qg = q0 + tr * 4 + i;
            float l[4];
            float tmax = -1e30f;
#pragma unroll
            for (int j = 0; j < 4; j++) {
                float2 sv = upk2(s2[i][j]);
                float s = sv.x + sv.y;
                // 50*tanh(s/(16*50)) = 50 - 100/(exp(s*2/800)+1)  (exact form)
                float E = __expf(s * 0.0025f);
                float lv = 50.0f - 100.0f / (E + 1.0f);
                int kg = kbase + tc + 16 * j;
                int dlt = qg - kg; if (dlt < 0) dlt = -dlt;
                l[j] = (dlt <= WINDOW) ? lv : -1e30f;
                tmax = fmaxf(tmax, l[j]);
            }
#pragma unroll
            for (int off = 8; off >= 1; off >>= 1)
                tmax = fmaxf(tmax, __shfl_xor_sync(0xffffffffu, tmax, off));
            float mnew = fmaxf(mrow[i], tmax);
            float psum = 0.f;
            float p[4];
#pragma unroll
            for (int j = 0; j < 4; j++) {
                p[j] = (l[j] > -1e29f) ? __expf(l[j] - mnew) : 0.f;
                psum += p[j];
            }
#pragma unroll
            for (int off = 8; off >= 1; off >>= 1)
                psum += __shfl_xor_sync(0xffffffffu, psum, off);
            float sc = __expf(mrow[i] - mnew);
            lrow[i] = lrow[i] * sc + psum;
            mrow[i] = mnew;
            scl[i] = sc;
#pragma unroll
            for (int j = 0; j < 4; j++)
                Ps[(tr * 4 + i) * PSTR + tc + 16 * j] = p[j];
        }

        // rescale O accumulators
#pragma unroll
        for (int i = 0; i < 4; i++) {
            if (scl[i] != 1.0f) {
                unsigned long long sp = pk2(scl[i], scl[i]);
#pragma unroll
                for (int jj = 0; jj < 4; jj++) {
                    o2[i][jj][0] = mul2(o2[i][jj][0], sp);
                    o2[i][jj][1] = mul2(o2[i][jj][1], sp);
                }
            }
        }
        __syncthreads();  // Ps visible

        // ---- O += P @ V ----
#pragma unroll 2
        for (int kk = 0; kk < AK; kk++) {
            unsigned long long vp[4][2];
#pragma unroll
            for (int jj = 0; jj < 4; jj++) {
                float4 v4 = *(const float4*)(Vs + kk * VSTR + tc * 4 + 64 * jj);
                vp[jj][0] = pk2(v4.x, v4.y);
                vp[jj][1] = pk2(v4.z, v4.w);
            }
#pragma unroll
            for (int i = 0; i < 4; i++) {
                float pv = Ps[(tr * 4 + i) * PSTR + kk];
                unsigned long long pp = pk2(pv, pv);
#pragma unroll
                for (int jj = 0; jj < 4; jj++) {
                    o2[i][jj][0] = fma2(pp, vp[jj][0], o2[i][jj][0]);
                    o2[i][jj][1] = fma2(pp, vp[jj][1], o2[i][jj][1]);
                }
            }
        }
    }

    // ---- normalize and write context ----
    float* Cg = Ctx + ((size_t)(b * SEQ + q0)) * QCOLS + h * HDIM;
#pragma unroll
    for (int i = 0; i < 4; i++) {
        float inv = 1.0f / lrow[i];
        unsigned long long ip = pk2(inv, inv);
#pragma unroll
        for (int jj = 0; jj < 4; jj++) {
            float2 lo = upk2(mul2(o2[i][jj][0], ip));
            float2 hi = upk2(mul2(o2[i][jj][1], ip));
            float4 o = make_float4(lo.x, lo.y, hi.x, hi.y);
            *(float4*)(Cg + (size_t)(tr * 4 + i) * QCOLS + tc * 4 + 64 * jj) = o;
        }
    }
}

// ---------------------------------------------------------------------------
// launch
// ---------------------------------------------------------------------------
extern "C" void kernel_launch(void* const* d_in, const int* in_sizes, int n_in,
                              void* d_out, int out_size)
{
    const float* hid = (const float*)d_in[0];
    const float* Wq  = (const float*)d_in[1];
    const float* Wk  = (const float*)d_in[2];
    const float* Wv  = (const float*)d_in[3];
    const float* Wo  = (const float*)d_in[4];
    float* out = (float*)d_out;

    float *Qb, *Kb, *Vb, *Cb;
    cudaGetSymbolAddress((void**)&Qb, g_Q);
    cudaGetSymbolAddress((void**)&Kb, g_K);
    cudaGetSymbolAddress((void**)&Vb, g_V);
    cudaGetSymbolAddress((void**)&Cb, g_Ctx);

    cudaFuncSetAttribute(attn_kernel, cudaFuncAttributeMaxDynamicSharedMemorySize,
                         ATTN_SMEM_BYTES);

    // RoPE tables (independent of GEMMs; tiny)
    rope_tables_kernel<<<(SEQ * 128 + 255) / 256, 256>>>();

    // projections
    sgemm_kernel<<<dim3(QCOLS / BN, MROWS / BM), 256>>>(hid, Wq, Qb, MROWS, QCOLS, EMBED);
    sgemm_kernel<<<dim3(KCOLS / BN, MROWS / BM), 256>>>(hid, Wk, Kb, MROWS, KCOLS, EMBED);
    sgemm_kernel<<<dim3(KCOLS / BN, MROWS / BM), 256>>>(hid, Wv, Vb, MROWS, KCOLS, EMBED);

    // RoPE
    rope_apply_kernel<<<(MROWS * NH  * 128 + 255) / 256, 256>>>(Qb, NH);
    rope_apply_kernel<<<(MROWS * NKV * 128 + 255) / 256, 256>>>(Kb, NKV);

    // attention
    attn_kernel<<<dim3(SEQ / AQ, BATCH * NH), 256, ATTN_SMEM_BYTES>>>(Qb, Kb, Vb, Cb);

    // output projection straight into d_out
    sgemm_kernel<<<dim3(EMBED / BN, MROWS / BM), 256>>>(Cb, Wo, out, MROWS, EMBED, QCOLS);
}

// round 5
// speedup vs baseline: 1.5687x; 1.5687x over previous
#include <cuda_runtime.h>
#include <cuda_bf16.h>
#include <math.h>
#include <stdint.h>

// ---------------------------------------------------------------------------
// Problem constants
// ---------------------------------------------------------------------------
#define BATCH   2
#define SEQ     2048
#define EMBED   3584
#define NH      16
#define NKV     8
#define HDIM    256
#define MROWS   (BATCH*SEQ)          // 4096
#define QCOLS   (NH*HDIM)            // 4096
#define KCOLS   (NKV*HDIM)           // 2048
#define WINDOW  1024

// ---------------------------------------------------------------------------
// Static device scratch (no cudaMalloc allowed)
// ---------------------------------------------------------------------------
__device__ float g_Q  [(size_t)MROWS*QCOLS];
__device__ float g_K  [(size_t)MROWS*KCOLS];
__device__ float g_V  [(size_t)MROWS*KCOLS];
__device__ float g_Ctx[(size_t)MROWS*QCOLS];
__device__ float g_cos[SEQ*(HDIM/2)];
__device__ float g_sin[SEQ*(HDIM/2)];

// bf16 hi/lo splits
__device__ __nv_bfloat16 g_Hh  [(size_t)MROWS*EMBED];
__device__ __nv_bfloat16 g_Hl  [(size_t)MROWS*EMBED];
__device__ __nv_bfloat16 g_WqtH[(size_t)QCOLS*EMBED];
__device__ __nv_bfloat16 g_WqtL[(size_t)QCOLS*EMBED];
__device__ __nv_bfloat16 g_WktH[(size_t)KCOLS*EMBED];
__device__ __nv_bfloat16 g_WktL[(size_t)KCOLS*EMBED];
__device__ __nv_bfloat16 g_WvtH[(size_t)KCOLS*EMBED];
__device__ __nv_bfloat16 g_WvtL[(size_t)KCOLS*EMBED];
__device__ __nv_bfloat16 g_WotH[(size_t)EMBED*QCOLS];
__device__ __nv_bfloat16 g_WotL[(size_t)EMBED*QCOLS];
__device__ __nv_bfloat16 g_Ch  [(size_t)MROWS*QCOLS];
__device__ __nv_bfloat16 g_Cl  [(size_t)MROWS*QCOLS];

// ---------------------------------------------------------------------------
// PTX helpers (sm_100-safe: no tcgen05, no clusters)
// ---------------------------------------------------------------------------
__device__ __forceinline__ uint32_t smem_u32(const void* p) {
    uint32_t a;
    asm("{ .reg .u64 t; cvta.to.shared.u64 t, %1; cvt.u32.u64 %0, t; }" : "=r"(a) : "l"(p));
    return a;
}
__device__ __forceinline__ void cp16(uint32_t dst, const void* src) {
    asm volatile("cp.async.cg.shared.global [%0], [%1], 16;" :: "r"(dst), "l"(src) : "memory");
}
__device__ __forceinline__ void ldmx4(uint32_t* r, uint32_t addr) {
    asm volatile("ldmatrix.sync.aligned.m8n8.x4.shared.b16 {%0,%1,%2,%3}, [%4];"
                 : "=r"(r[0]), "=r"(r[1]), "=r"(r[2]), "=r"(r[3]) : "r"(addr));
}
__device__ __forceinline__ void mma_bf16(float* c, const uint32_t* a,
                                         uint32_t b0, uint32_t b1) {
    asm volatile(
        "mma.sync.aligned.m16n8k16.row.col.f32.bf16.bf16.f32 "
        "{%0,%1,%2,%3}, {%4,%5,%6,%7}, {%8,%9}, {%0,%1,%2,%3};"
        : "+f"(c[0]), "+f"(c[1]), "+f"(c[2]), "+f"(c[3])
        : "r"(a[0]), "r"(a[1]), "r"(a[2]), "r"(a[3]), "r"(b0), "r"(b1));
}

// ---------------------------------------------------------------------------
// f32x2 packed math (for the fp32 attention kernel)
// ---------------------------------------------------------------------------
__device__ __forceinline__ unsigned long long pk2(float lo, float hi) {
    unsigned long long r;
    asm("mov.b64 %0, {%1, %2};" : "=l"(r) : "f"(lo), "f"(hi));
    return r;
}
__device__ __forceinline__ float2 upk2(unsigned long long v) {
    float2 r;
    asm("mov.b64 {%0, %1}, %2;" : "=f"(r.x), "=f"(r.y) : "l"(v));
    return r;
}
__device__ __forceinline__ unsigned long long fma2(unsigned long long a,
                                                   unsigned long long b,
                                                   unsigned long long c) {
    unsigned long long d;
    asm("fma.rn.f32x2 %0, %1, %2, %3;" : "=l"(d) : "l"(a), "l"(b), "l"(c));
    return d;
}
__device__ __forceinline__ unsigned long long mul2(unsigned long long a,
                                                   unsigned long long b) {
    unsigned long long d;
    asm("mul.rn.f32x2 %0, %1, %2;" : "=l"(d) : "l"(a), "l"(b));
    return d;
}

// ---------------------------------------------------------------------------
// fp32 -> bf16 hi/lo split (vectorized)
// ---------------------------------------------------------------------------
__global__ void split_kernel(const float* __restrict__ in,
                             __nv_bfloat16* __restrict__ hi,
                             __nv_bfloat16* __restrict__ lo, int n4)
{
    int i = blockIdx.x * 256 + threadIdx.x;
    if (i >= n4) return;
    float4 v = ((const float4*)in)[i];
    __nv_bfloat16 h0 = __float2bfloat16(v.x);
    __nv_bfloat16 h1 = __float2bfloat16(v.y);
    __nv_bfloat16 h2 = __float2bfloat16(v.z);
    __nv_bfloat16 h3 = __float2bfloat16(v.w);
    __nv_bfloat16 l0 = __float2bfloat16(v.x - __bfloat162float(h0));
    __nv_bfloat16 l1 = __float2bfloat16(v.y - __bfloat162float(h1));
    __nv_bfloat16 l2 = __float2bfloat16(v.z - __bfloat162float(h2));
    __nv_bfloat16 l3 = __float2bfloat16(v.w - __bfloat162float(h3));
    ((__nv_bfloat162*)hi)[2*i]   = __halves2bfloat162(h0, h1);
    ((__nv_bfloat162*)hi)[2*i+1] = __halves2bfloat162(h2, h3);
    ((__nv_bfloat162*)lo)[2*i]   = __halves2bfloat162(l0, l1);
    ((__nv_bfloat162*)lo)[2*i+1] = __halves2bfloat162(l2, l3);
}

// ---------------------------------------------------------------------------
// Transpose + split: W [K,N] fp32 -> Th/Tl [N,K] bf16
// ---------------------------------------------------------------------------
__global__ void tsplit_kernel(const float* __restrict__ W,
                              __nv_bfloat16* __restrict__ Th,
                              __nv_bfloat16* __restrict__ Tl, int K, int N)
{
    __shared__ float t[32][33];
    int n0 = blockIdx.x * 32, k0 = blockIdx.y * 32;
    int tx = threadIdx.x, ty = threadIdx.y;
#pragma unroll
    for (int i = 0; i < 32; i += 8)
        t[ty + i][tx] = W[(size_t)(k0 + ty + i) * N + n0 + tx];
    __syncthreads();
#pragma unroll
    for (int i = 0; i < 32; i += 8) {
        float v = t[tx][ty + i];
        __nv_bfloat16 h = __float2bfloat16(v);
        __nv_bfloat16 l = __float2bfloat16(v - __bfloat162float(h));
        size_t o = (size_t)(n0 + ty + i) * K + k0 + tx;
        Th[o] = h;
        Tl[o] = l;
    }
}

// ---------------------------------------------------------------------------
// mma.sync bf16x3 GEMM: C[M,N] fp32 = (Ah+Al)[M,K] @ (Bh+Bl)[N,K]^T
// 128x128 CTA tile, 8 warps (2x4 -> warp tile 64x32), K-chunk 32,
// 3-stage cp.async pipeline. SMEM rows padded to 40 bf16 (80 B).
// ---------------------------------------------------------------------------
#define GKC       32                 // K elements per chunk
#define GSTRIDE   40                 // smem row stride in bf16 (80 B)
#define GTILE_B   (128*GSTRIDE*2)    // 10240 B per tile
#define GSTAGE_B  (4*GTILE_B)        // Ah, Al, Bh, Bl
#define GEMM_SMEM (3*GSTAGE_B)       // 122880 B

__device__ __forceinline__ void fill_stage(uint32_t stb,
                                           const __nv_bfloat16* Ah0,
                                           const __nv_bfloat16* Al0,
                                           const __nv_bfloat16* Bh0,
                                           const __nv_bfloat16* Bl0,
                                           int K, int tid)
{
    const __nv_bfloat16* srcs[4] = {Ah0, Al0, Bh0, Bl0};
#pragma unroll
    for (int t = 0; t < 4; t++) {
        uint32_t tb = stb + t * GTILE_B;
        const char* s = (const char*)srcs[t];
#pragma unroll
        for (int i = 0; i < 2; i++) {
            int id = tid + i * 256;          // 0..511
            int row = id >> 2, ch = id & 3;  // 128 rows x 4 x 16B
            cp16(tb + row * (GSTRIDE * 2) + ch * 16,
                 s + (size_t)row * K * 2 + ch * 16);
        }
    }
    asm volatile("cp.async.commit_group;" ::: "memory");
}

__global__ void __launch_bounds__(256, 1)
gemm_mma_kernel(const __nv_bfloat16* __restrict__ Ah,
                const __nv_bfloat16* __restrict__ Al,
                const __nv_bfloat16* __restrict__ Bh,
                const __nv_bfloat16* __restrict__ Bl,
                float* __restrict__ C, int M, int N, int K)
{
    extern __shared__ char gsm[];
    const uint32_t sbase = smem_u32(gsm);
    const int tid = threadIdx.x;
    const int wid = tid >> 5, lane = tid & 31;
    const int wm = wid & 1, wn = wid >> 1;     // 2 x 4 warp grid
    const int m0 = blockIdx.y * 128, n0 = blockIdx.x * 128;

    // ldmatrix per-thread byte offsets within a tile
    uint32_t a_off[4], b_off[2];
#pragma unroll
    for (int mt = 0; mt < 4; mt++)
        a_off[mt] = ((wm * 64 + mt * 16 + (lane & 15)) * GSTRIDE
                     + (lane >> 4) * 8) * 2;
#pragma unroll
    for (int np = 0; np < 2; np++)
        b_off[np] = ((wn * 32 + np * 16 + (lane & 7) + ((lane >> 4) & 1) * 8) * GSTRIDE
                     + ((lane >> 3) & 1) * 8) * 2;

    const __nv_bfloat16* Ah0 = Ah + (size_t)m0 * K;
    const __nv_bfloat16* Al0 = Al + (size_t)m0 * K;
    const __nv_bfloat16* Bh0 = Bh + (size_t)n0 * K;
    const __nv_bfloat16* Bl0 = Bl + (size_t)n0 * K;

    float acc[4][4][4];
#pragma unroll
    for (int mt = 0; mt < 4; mt++)
#pragma unroll
        for (int nt = 0; nt < 4; nt++)
#pragma unroll
            for (int r = 0; r < 4; r++) acc[mt][nt][r] = 0.f;

    const int NC = K / GKC;

    // prologue: 3 stages in flight
#pragma unroll
    for (int c = 0; c < 3; c++)
        fill_stage(sbase + c * GSTAGE_B, Ah0 + c * GKC, Al0 + c * GKC,
                   Bh0 + c * GKC, Bl0 + c * GKC, K, tid);

    for (int c = 0; c < NC; c++) {
        const uint32_t stb = sbase + (c % 3) * GSTAGE_B;
        asm volatile("cp.async.wait_group %0;" :: "n"(2) : "memory");
        __syncthreads();

#pragma unroll
        for (int ks = 0; ks < 2; ks++) {
            const uint32_t ko = ks * 32;   // 16 bf16 = 32 B along k
            uint32_t ah[4][4], al[4][4], bh[2][4], bl[2][4];
#pragma unroll
            for (int mt = 0; mt < 4; mt++) {
                ldmx4(ah[mt], stb + 0 * GTILE_B + a_off[mt] + ko);
                ldmx4(al[mt], stb + 1 * GTILE_B + a_off[mt] + ko);
            }
#pragma unroll
            for (int np = 0; np < 2; np++) {
                ldmx4(bh[np], stb + 2 * GTILE_B + b_off[np] + ko);
                ldmx4(bl[np], stb + 3 * GTILE_B + b_off[np] + ko);
            }
#pragma unroll
            for (int mt = 0; mt < 4; mt++)
#pragma unroll
                for (int nt = 0; nt < 4; nt++) {
                    const int np = nt >> 1, bi = (nt & 1) * 2;
                    mma_bf16(acc[mt][nt], ah[mt], bh[np][bi], bh[np][bi + 1]);
                    mma_bf16(acc[mt][nt], al[mt], bh[np][bi], bh[np][bi + 1]);
                    mma_bf16(acc[mt][nt], ah[mt], bl[np][bi], bl[np][bi + 1]);
                }
        }

        __syncthreads();   // all warps done reading this stage
        const int cn = c + 3;
        if (cn < NC)
            fill_stage(stb, Ah0 + cn * GKC, Al0 + cn * GKC,
                       Bh0 + cn * GKC, Bl0 + cn * GKC, K, tid);
    }

    // epilogue: fragment layout -> global
    const int rr = lane >> 2, cc = (lane & 3) * 2;
#pragma unroll
    for (int mt = 0; mt < 4; mt++) {
        const size_t mA = (size_t)(m0 + wm * 64 + mt * 16 + rr);
#pragma unroll
        for (int nt = 0; nt < 4; nt++) {
            const int n = n0 + wn * 32 + nt * 8 + cc;
            *(float2*)(C + mA * N + n) =
                make_float2(acc[mt][nt][0], acc[mt][nt][1]);
            *(float2*)(C + (mA + 8) * N + n) =
                make_float2(acc[mt][nt][2], acc[mt][nt][3]);
        }
    }
}

// ---------------------------------------------------------------------------
// RoPE tables (double precision)
// ---------------------------------------------------------------------------
__global__ void rope_tables_kernel()
{
    int idx = blockIdx.x * 256 + threadIdx.x;
    if (idx >= SEQ * (HDIM / 2)) return;
    int i = idx & 127;
    int pos = idx >> 7;
    double invf = pow(10000.0, -(double)(2 * i) / (double)HDIM);
    double ang = (double)pos * invf;
    g_cos[idx] = (float)cos(ang);
    g_sin[idx] = (float)sin(ang);
}

// ---------------------------------------------------------------------------
// RoPE apply (in place), X is [MROWS, heads*HDIM]
// ---------------------------------------------------------------------------
__global__ void rope_apply_kernel(float* __restrict__ X, int heads)
{
    int idx = blockIdx.x * 256 + threadIdx.x;
    int total = MROWS * heads * (HDIM / 2);
    if (idx >= total) return;
    int i = idx & 127;
    int t = idx >> 7;
    int h = t % heads;
    int m = t / heads;
    int pos = m & (SEQ - 1);
    float c = g_cos[pos * 128 + i];
    float s = g_sin[pos * 128 + i];
    float* p = X + (size_t)m * (heads * HDIM) + h * HDIM + i;
    float x1 = p[0];
    float x2 = p[128];
    p[0]   = x1 * c - x2 * s;
    p[128] = x2 * c + x1 * s;
}

// ---------------------------------------------------------------------------
// Fused flash attention (fp32, f32x2 FMAs) — unchanged from passing R2 kernel
// ---------------------------------------------------------------------------
#define AQ 64
#define AK 64
#define QSTR 260
#define KSTR 260
#define VSTR 256
#define PSTR 68
#define ATTN_SMEM_FLOATS (AQ*QSTR + AK*KSTR + AK*VSTR + AQ*PSTR)
#define ATTN_SMEM_BYTES  (ATTN_SMEM_FLOATS * 4)

__global__ void __launch_bounds__(256) attn_kernel(
    const float* __restrict__ Q, const float* __restrict__ K,
    const float* __restrict__ V, float* __restrict__ Ctx)
{
    extern __shared__ float sm[];
    float* Qs = sm;
    float* Ks = Qs + AQ * QSTR;
    float* Vs = Ks + AK * KSTR;
    float* Ps = Vs + AK * VSTR;

    const int bh = blockIdx.y;
    const int b  = bh >> 4;
    const int h  = bh & 15;
    const int kvh = h >> 1;
    const int q0 = blockIdx.x * AQ;

    const int tid = threadIdx.x;
    const int tr = tid >> 4;
    const int tc = tid & 15;

    const float* Qg = Q + ((size_t)(b * SEQ + q0)) * QCOLS + h * HDIM;
    const float* Kg = K + ((size_t)(b * SEQ)) * KCOLS + kvh * HDIM;
    const float* Vg = V + ((size_t)(b * SEQ)) * KCOLS + kvh * HDIM;

#pragma unroll
    for (int t = 0; t < 16; t++) {
        int idx = tid + t * 256;
        int r = idx >> 6, c4 = idx & 63;
        float4 v = *(const float4*)(Qg + (size_t)r * QCOLS + c4 * 4);
        *(float4*)(Qs + r * QSTR + c4 * 4) = v;
    }

    unsigned long long o2[4][4][2];
    const unsigned long long z = pk2(0.f, 0.f);
#pragma unroll
    for (int i = 0; i < 4; i++)
#pragma unroll
        for (int jj = 0; jj < 4; jj++) { o2[i][jj][0] = z; o2[i][jj][1] = z; }

    float mrow[4] = {-1e30f, -1e30f, -1e30f, -1e30f};
    float lrow[4] = {0.f, 0.f, 0.f, 0.f};

    int klo = q0 - WINDOW;            if (klo < 0) klo = 0;
    int khi = q0 + AQ + WINDOW;       if (khi > SEQ) khi = SEQ;
    const int kt0 = klo >> 6;
    const int kt1 = (khi >> 6) - 1;

    for (int kt = kt0; kt <= kt1; kt++) {
        __syncthreads();
        const int kbase = kt * AK;
#pragma unroll
        for (int t = 0; t < 16; t++) {
            int idx = tid + t * 256;
            int r = idx >> 6, c4 = idx & 63;
            float4 kv = *(const float4*)(Kg + (size_t)(kbase + r) * KCOLS + c4 * 4);
            *(float4*)(Ks + r * KSTR + c4 * 4) = kv;
            float4 vv = *(const float4*)(Vg + (size_t)(kbase + r) * KCOLS + c4 * 4);
            *(float4*)(Vs + r * VSTR + c4 * 4) = vv;
        }
        __syncthreads();

        unsigned long long s2[4][4];
#pragma unroll
        for (int i = 0; i < 4; i++)
#pragma unroll
            for (int j = 0; j < 4; j++) s2[i][j] = z;

#pragma unroll 4
        for (int d = 0; d < HDIM; d += 4) {
            unsigned long long qp0[4], qp1[4];
#pragma unroll
            for (int i = 0; i < 4; i++) {
                float4 q4 = *(const float4*)(Qs + (tr * 4 + i) * QSTR + d);
                qp0[i] = pk2(q4.x, q4.y);
                qp1[i] = pk2(q4.z, q4.w);
            }
#pragma unroll
            for (int j = 0; j < 4; j++) {
                float4 k4 = *(const float4*)(Ks + (tc + 16 * j) * KSTR + d);
                unsigned long long kp0 = pk2(k4.x, k4.y);
                unsigned long long kp1 = pk2(k4.z, k4.w);
#pragma unroll
                for (int i = 0; i < 4; i++) {
                    s2[i][j] = fma2(qp0[i], kp0, s2[i][j]);
                    s2[i][j] = fma2(qp1[i], kp1, s2[i][j]);
                }
            }
        }

        float scl[4];
#pragma unroll
        for (int i = 0; i < 4; i++) {
            const int qg = q0 + tr * 4 + i;
            float l[4];
            float tmax = -1e30f;
#pragma unroll
            for (int j = 0; j < 4; j++) {
                float2 sv = upk2(s2[i][j]);
                float s = sv.x + sv.y;
                float E = __expf(s * 0.0025f);
                float lv = 50.0f - 100.0f / (E + 1.0f);
                int kg = kbase + tc + 16 * j;
                int dlt = qg - kg; if (dlt < 0) dlt = -dlt;
                l[j] = (dlt <= WINDOW) ? lv : -1e30f;
                tmax = fmaxf(tmax, l[j]);
            }
#pragma unroll
            for (int off = 8; off >= 1; off >>= 1)
                tmax = fmaxf(tmax, __shfl_xor_sync(0xffffffffu, tmax, off));
            float mnew = fmaxf(mrow[i], tmax);
            float psum = 0.f;
            float p[4];
#pragma unroll
            for (int j = 0; j < 4; j++) {
                p[j] = (l[j] > -1e29f) ? __expf(l[j] - mnew) : 0.f;
                psum += p[j];
            }
#pragma unroll
            for (int off = 8; off >= 1; off >>= 1)
                psum += __shfl_xor_sync(0xffffffffu, psum, off);
            float sc = __expf(mrow[i] - mnew);
            lrow[i] = lrow[i] * sc + psum;
            mrow[i] = mnew;
            scl[i] = sc;
#pragma unroll
            for (int j = 0; j < 4; j++)
                Ps[(tr * 4 + i) * PSTR + tc + 16 * j] = p[j];
        }

#pragma unroll
        for (int i = 0; i < 4; i++) {
            if (scl[i] != 1.0f) {
                unsigned long long sp = pk2(scl[i], scl[i]);
#pragma unroll
                for (int jj = 0; jj < 4; jj++) {
                    o2[i][jj][0] = mul2(o2[i][jj][0], sp);
                    o2[i][jj][1] = mul2(o2[i][jj][1], sp);
                }
            }
        }
        __syncthreads();

#pragma unroll 2
        for (int kk = 0; kk < AK; kk++) {
            unsigned long long vp[4][2];
#pragma unroll
            for (int jj = 0; jj < 4; jj++) {
                float4 v4 = *(const float4*)(Vs + kk * VSTR + tc * 4 + 64 * jj);
                vp[jj][0] = pk2(v4.x, v4.y);
                vp[jj][1] = pk2(v4.z, v4.w);
            }
#pragma unroll
            for (int i = 0; i < 4; i++) {
                float pv = Ps[(tr * 4 + i) * PSTR + kk];
                unsigned long long pp = pk2(pv, pv);
#pragma unroll
                for (int jj = 0; jj < 4; jj++) {
                    o2[i][jj][0] = fma2(pp, vp[jj][0], o2[i][jj][0]);
                    o2[i][jj][1] = fma2(pp, vp[jj][1], o2[i][jj][1]);
                }
            }
        }
    }

    float* Cg = Ctx + ((size_t)(b * SEQ + q0)) * QCOLS + h * HDIM;
#pragma unroll
    for (int i = 0; i < 4; i++) {
        float inv = 1.0f / lrow[i];
        unsigned long long ip = pk2(inv, inv);
#pragma unroll
        for (int jj = 0; jj < 4; jj++) {
            float2 lo = upk2(mul2(o2[i][jj][0], ip));
            float2 hi = upk2(mul2(o2[i][jj][1], ip));
            float4 o = make_float4(lo.x, lo.y, hi.x, hi.y);
            *(float4*)(Cg + (size_t)(tr * 4 + i) * QCOLS + tc * 4 + 64 * jj) = o;
        }
    }
}

// ---------------------------------------------------------------------------
// launch
// ---------------------------------------------------------------------------
extern "C" void kernel_launch(void* const* d_in, const int* in_sizes, int n_in,
                              void* d_out, int out_size)
{
    const float* hid = (const float*)d_in[0];
    const float* Wq  = (const float*)d_in[1];
    const float* Wk  = (const float*)d_in[2];
    const float* Wv  = (const float*)d_in[3];
    const float* Wo  = (const float*)d_in[4];
    float* out = (float*)d_out;

    float *Qb, *Kb, *Vb, *Cb;
    cudaGetSymbolAddress((void**)&Qb, g_Q);
    cudaGetSymbolAddress((void**)&Kb, g_K);
    cudaGetSymbolAddress((void**)&Vb, g_V);
    cudaGetSymbolAddress((void**)&Cb, g_Ctx);

    __nv_bfloat16 *Hh, *Hl, *WqtH, *WqtL, *WktH, *WktL, *WvtH, *WvtL, *WotH, *WotL, *Ch, *Cl;
    cudaGetSymbolAddress((void**)&Hh,   g_Hh);
    cudaGetSymbolAddress((void**)&Hl,   g_Hl);
    cudaGetSymbolAddress((void**)&WqtH, g_WqtH);
    cudaGetSymbolAddress((void**)&WqtL, g_WqtL);
    cudaGetSymbolAddress((void**)&WktH, g_WktH);
    cudaGetSymbolAddress((void**)&WktL, g_WktL);
    cudaGetSymbolAddress((void**)&WvtH, g_WvtH);
    cudaGetSymbolAddress((void**)&WvtL, g_WvtL);
    cudaGetSymbolAddress((void**)&WotH, g_WotH);
    cudaGetSymbolAddress((void**)&WotL, g_WotL);
    cudaGetSymbolAddress((void**)&Ch,   g_Ch);
    cudaGetSymbolAddress((void**)&Cl,   g_Cl);

    cudaFuncSetAttribute(attn_kernel, cudaFuncAttributeMaxDynamicSharedMemorySize,
                         ATTN_SMEM_BYTES);
    cudaFuncSetAttribute(gemm_mma_kernel, cudaFuncAttributeMaxDynamicSharedMemorySize,
                         GEMM_SMEM);

    rope_tables_kernel<<<(SEQ * 128 + 255) / 256, 256>>>();

    // splits / transposes
    split_kernel<<<(MROWS * EMBED / 4 + 255) / 256, 256>>>(hid, Hh, Hl, MROWS * EMBED / 4);
    tsplit_kernel<<<dim3(QCOLS / 32, EMBED / 32), dim3(32, 8)>>>(Wq, WqtH, WqtL, EMBED, QCOLS);
    tsplit_kernel<<<dim3(KCOLS / 32, EMBED / 32), dim3(32, 8)>>>(Wk, WktH, WktL, EMBED, KCOLS);
    tsplit_kernel<<<dim3(KCOLS / 32, EMBED / 32), dim3(32, 8)>>>(Wv, WvtH, WvtL, EMBED, KCOLS);
    tsplit_kernel<<<dim3(EMBED / 32, QCOLS / 32), dim3(32, 8)>>>(Wo, WotH, WotL, QCOLS, EMBED);

    // projections (mma.sync bf16x3)
    gemm_mma_kernel<<<dim3(QCOLS / 128, MROWS / 128), 256, GEMM_SMEM>>>(
        Hh, Hl, WqtH, WqtL, Qb, MROWS, QCOLS, EMBED);
    gemm_mma_kernel<<<dim3(KCOLS / 128, MROWS / 128), 256, GEMM_SMEM>>>(
        Hh, Hl, WktH, WktL, Kb, MROWS, KCOLS, EMBED);
    gemm_mma_kernel<<<dim3(KCOLS / 128, MROWS / 128), 256, GEMM_SMEM>>>(
        Hh, Hl, WvtH, WvtL, Vb, MROWS, KCOLS, EMBED);

    // RoPE
    rope_apply_kernel<<<(MROWS * NH  * 128 + 255) / 256, 256>>>(Qb, NH);
    rope_apply_kernel<<<(MROWS * NKV * 128 + 255) / 256, 256>>>(Kb, NKV);

    // attention
    attn_kernel<<<dim3(SEQ / AQ, BATCH * NH), 256, ATTN_SMEM_BYTES>>>(Qb, Kb, Vb, Cb);

    // output projection: split context, then mma GEMM straight into d_out
    split_kernel<<<(MROWS * QCOLS / 4 + 255) / 256, 256>>>(Cb, Ch, Cl, MROWS * QCOLS / 4);
    gemm_mma_kernel<<<dim3(EMBED / 128, MROWS / 128), 256, GEMM_SMEM>>>(
        Ch, Cl, WotH, WotL, out, MROWS, EMBED, QCOLS);
}

// round 7
// speedup vs baseline: 2.1381x; 1.3630x over previous
#include <cuda_runtime.h>
#include <cuda_bf16.h>
#include <math.h>
#include <stdint.h>

// ---------------------------------------------------------------------------
// Problem constants
// ---------------------------------------------------------------------------
#define BATCH   2
#define SEQ     2048
#define EMBED   3584
#define NH      16
#define NKV     8
#define HDIM    256
#define MROWS   (BATCH*SEQ)          // 4096
#define QCOLS   (NH*HDIM)            // 4096
#define KCOLS   (NKV*HDIM)           // 2048
#define WINDOW  1024

// ---------------------------------------------------------------------------
// Static device scratch (no cudaMalloc allowed)
// ---------------------------------------------------------------------------
__device__ float g_Q  [(size_t)MROWS*QCOLS];
__device__ float g_K  [(size_t)MROWS*KCOLS];
__device__ float g_V  [(size_t)MROWS*KCOLS];
__device__ float g_cos[SEQ*(HDIM/2)];
__device__ float g_sin[SEQ*(HDIM/2)];

// bf16 hi/lo splits
__device__ __nv_bfloat16 g_Hh  [(size_t)MROWS*EMBED];
__device__ __nv_bfloat16 g_Hl  [(size_t)MROWS*EMBED];
__device__ __nv_bfloat16 g_WqtH[(size_t)QCOLS*EMBED];
__device__ __nv_bfloat16 g_WqtL[(size_t)QCOLS*EMBED];
__device__ __nv_bfloat16 g_WktH[(size_t)KCOLS*EMBED];
__device__ __nv_bfloat16 g_WktL[(size_t)KCOLS*EMBED];
__device__ __nv_bfloat16 g_WvtH[(size_t)KCOLS*EMBED];
__device__ __nv_bfloat16 g_WvtL[(size_t)KCOLS*EMBED];
__device__ __nv_bfloat16 g_WotH[(size_t)EMBED*QCOLS];
__device__ __nv_bfloat16 g_WotL[(size_t)EMBED*QCOLS];
__device__ __nv_bfloat16 g_Ch  [(size_t)MROWS*QCOLS];
__device__ __nv_bfloat16 g_Cl  [(size_t)MROWS*QCOLS];

// attention operands (bf16 splits)
__device__ __nv_bfloat16 g_Qh [(size_t)MROWS*QCOLS];
__device__ __nv_bfloat16 g_Ql [(size_t)MROWS*QCOLS];
__device__ __nv_bfloat16 g_Kh [(size_t)MROWS*KCOLS];
__device__ __nv_bfloat16 g_Kl [(size_t)MROWS*KCOLS];
__device__ __nv_bfloat16 g_VtH[(size_t)MROWS*KCOLS];   // per-batch transposed [KCOLS][SEQ]
__device__ __nv_bfloat16 g_VtL[(size_t)MROWS*KCOLS];

// ---------------------------------------------------------------------------
// PTX helpers (sm_100-safe: no tcgen05, no clusters)
// ---------------------------------------------------------------------------
__device__ __forceinline__ uint32_t smem_u32(const void* p) {
    uint32_t a;
    asm("{ .reg .u64 t; cvta.to.shared.u64 t, %1; cvt.u32.u64 %0, t; }" : "=r"(a) : "l"(p));
    return a;
}
__device__ __forceinline__ void cp16(uint32_t dst, const void* src) {
    asm volatile("cp.async.cg.shared.global [%0], [%1], 16;" :: "r"(dst), "l"(src) : "memory");
}
__device__ __forceinline__ void ldmx4(uint32_t* r, uint32_t addr) {
    asm volatile("ldmatrix.sync.aligned.m8n8.x4.shared.b16 {%0,%1,%2,%3}, [%4];"
                 : "=r"(r[0]), "=r"(r[1]), "=r"(r[2]), "=r"(r[3]) : "r"(addr));
}
__device__ __forceinline__ void mma_bf16(float* c, const uint32_t* a,
                                         uint32_t b0, uint32_t b1) {
    asm volatile(
        "mma.sync.aligned.m16n8k16.row.col.f32.bf16.bf16.f32 "
        "{%0,%1,%2,%3}, {%4,%5,%6,%7}, {%8,%9}, {%0,%1,%2,%3};"
        : "+f"(c[0]), "+f"(c[1]), "+f"(c[2]), "+f"(c[3])
        : "r"(a[0]), "r"(a[1]), "r"(a[2]), "r"(a[3]), "r"(b0), "r"(b1));
}

// FMA-pipe exp (no MUFU): e^x for |x| <= ~85, rel err ~1.5e-7
__device__ __forceinline__ float fexp(float x) {
    float y  = x * 1.4426950408889634f;          // log2(e)
    float fm = y + 12582912.0f;                  // round-to-nearest via magic
    float nf = fm - 12582912.0f;
    float f  = y - nf;                           // [-0.5, 0.5]
    int   sc = ((__float_as_int(fm) - 0x4B400000) + 127) << 23;
    float t  = f * 0.6931471805599453f;
    float p  = 1.0f + t*(1.0f + t*(0.5f + t*(0.16666667f +
               t*(0.041666667f + t*(0.008333334f + t*0.0013888889f)))));
    return p * __int_as_float(sc);
}
// FMA-pipe reciprocal (bit-hack + 3 Newton), rel err ~1e-10 for d in [1,4]
__device__ __forceinline__ float frcp(float d) {
    float r = __int_as_float(0x7EF311C3 - __float_as_int(d));
    r = r * (2.0f - d * r);
    r = r * (2.0f - d * r);
    r = r * (2.0f - d * r);
    return r;
}

// ---------------------------------------------------------------------------
// fp32 -> bf16 hi/lo split (vectorized)
// ---------------------------------------------------------------------------
__global__ void split_kernel(const float* __restrict__ in,
                             __nv_bfloat16* __restrict__ hi,
                             __nv_bfloat16* __restrict__ lo, int n4)
{
    int i = blockIdx.x * 256 + threadIdx.x;
    if (i >= n4) return;
    float4 v = ((const float4*)in)[i];
    __nv_bfloat16 h0 = __float2bfloat16(v.x);
    __nv_bfloat16 h1 = __float2bfloat16(v.y);
    __nv_bfloat16 h2 = __float2bfloat16(v.z);
    __nv_bfloat16 h3 = __float2bfloat16(v.w);
    __nv_bfloat16 l0 = __float2bfloat16(v.x - __bfloat162float(h0));
    __nv_bfloat16 l1 = __float2bfloat16(v.y - __bfloat162float(h1));
    __nv_bfloat16 l2 = __float2bfloat16(v.z - __bfloat162float(h2));
    __nv_bfloat16 l3 = __float2bfloat16(v.w - __bfloat162float(h3));
    ((__nv_bfloat162*)hi)[2*i]   = __halves2bfloat162(h0, h1);
    ((__nv_bfloat162*)hi)[2*i+1] = __halves2bfloat162(h2, h3);
    ((__nv_bfloat162*)lo)[2*i]   = __halves2bfloat162(l0, l1);
    ((__nv_bfloat162*)lo)[2*i+1] = __halves2bfloat162(l2, l3);
}

// ---------------------------------------------------------------------------
// Transpose + split: W [K,N] fp32 -> Th/Tl [N,K] bf16
// ---------------------------------------------------------------------------
__global__ void tsplit_kernel(const float* __restrict__ W,
                              __nv_bfloat16* __restrict__ Th,
                              __nv_bfloat16* __restrict__ Tl, int K, int N)
{
    __shared__ float t[32][33];
    int n0 = blockIdx.x * 32, k0 = blockIdx.y * 32;
    int tx = threadIdx.x, ty = threadIdx.y;
#pragma unroll
    for (int i = 0; i < 32; i += 8)
        t[ty + i][tx] = W[(size_t)(k0 + ty + i) * N + n0 + tx];
    __syncthreads();
#pragma unroll
    for (int i = 0; i < 32; i += 8) {
        float v = t[tx][ty + i];
        __nv_bfloat16 h = __float2bfloat16(v);
        __nv_bfloat16 l = __float2bfloat16(v - __bfloat162float(h));
        size_t o = (size_t)(n0 + ty + i) * K + k0 + tx;
        Th[o] = h;
        Tl[o] = l;
    }
}

// ---------------------------------------------------------------------------
// V transpose+split per batch: g_V [b*SEQ+s][KCOLS] -> Vt [b][KCOLS][SEQ]
// ---------------------------------------------------------------------------
__global__ void vtsplit_kernel(const float* __restrict__ V,
                               __nv_bfloat16* __restrict__ Th,
                               __nv_bfloat16* __restrict__ Tl)
{
    __shared__ float t[32][33];
    int s0 = blockIdx.x * 32, c0 = blockIdx.y * 32, b = blockIdx.z;
    int tx = threadIdx.x, ty = threadIdx.y;
#pragma unroll
    for (int i = 0; i < 32; i += 8)
        t[ty + i][tx] = V[((size_t)b * SEQ + s0 + ty + i) * KCOLS + c0 + tx];
    __syncthreads();
#pragma unroll
    for (int i = 0; i < 32; i += 8) {
        float v = t[tx][ty + i];
        __nv_bfloat16 h = __float2bfloat16(v);
        __nv_bfloat16 l = __float2bfloat16(v - __bfloat162float(h));
        size_t o = ((size_t)b * KCOLS + c0 + ty + i) * SEQ + s0 + tx;
        Th[o] = h;
        Tl[o] = l;
    }
}

// ---------------------------------------------------------------------------
// mma.sync bf16x3 GEMM (unchanged from passing R5 kernel)
// ---------------------------------------------------------------------------
#define GKC       32
#define GSTRIDE   40
#define GTILE_B   (128*GSTRIDE*2)
#define GSTAGE_B  (4*GTILE_B)
#define GEMM_SMEM (3*GSTAGE_B)

__device__ __forceinline__ void fill_stage(uint32_t stb,
                                           const __nv_bfloat16* Ah0,
                                           const __nv_bfloat16* Al0,
                                           const __nv_bfloat16* Bh0,
                                           const __nv_bfloat16* Bl0,
                                           int K, int tid)
{
    const __nv_bfloat16* srcs[4] = {Ah0, Al0, Bh0, Bl0};
#pragma unroll
    for (int t = 0; t < 4; t++) {
        uint32_t tb = stb + t * GTILE_B;
        const char* s = (const char*)srcs[t];
#pragma unroll
        for (int i = 0; i < 2; i++) {
            int id = tid + i * 256;
            int row = id >> 2, ch = id & 3;
            cp16(tb + row * (GSTRIDE * 2) + ch * 16,
                 s + (size_t)row * K * 2 + ch * 16);
        }
    }
    asm volatile("cp.async.commit_group;" ::: "memory");
}

__global__ void __launch_bounds__(256, 1)
gemm_mma_kernel(const __nv_bfloat16* __restrict__ Ah,
                const __nv_bfloat16* __restrict__ Al,
                const __nv_bfloat16* __restrict__ Bh,
                const __nv_bfloat16* __restrict__ Bl,
                float* __restrict__ C, int M, int N, int K)
{
    extern __shared__ char gsm[];
    const uint32_t sbase = smem_u32(gsm);
    const int tid = threadIdx.x;
    const int wid = tid >> 5, lane = tid & 31;
    const int wm = wid & 1, wn = wid >> 1;
    const int m0 = blockIdx.y * 128, n0 = blockIdx.x * 128;

    uint32_t a_off[4], b_off[2];
#pragma unroll
    for (int mt = 0; mt < 4; mt++)
        a_off[mt] = ((wm * 64 + mt * 16 + (lane & 15)) * GSTRIDE
                     + (lane >> 4) * 8) * 2;
#pragma unroll
    for (int np = 0; np < 2; np++)
        b_off[np] = ((wn * 32 + np * 16 + (lane & 7) + ((lane >> 4) & 1) * 8) * GSTRIDE
                     + ((lane >> 3) & 1) * 8) * 2;

    const __nv_bfloat16* Ah0 = Ah + (size_t)m0 * K;
    const __nv_bfloat16* Al0 = Al + (size_t)m0 * K;
    const __nv_bfloat16* Bh0 = Bh + (size_t)n0 * K;
    const __nv_bfloat16* Bl0 = Bl + (size_t)n0 * K;

    float acc[4][4][4];
#pragma unroll
    for (int mt = 0; mt < 4; mt++)
#pragma unroll
        for (int nt = 0; nt < 4; nt++)
#pragma unroll
            for (int r = 0; r < 4; r++) acc[mt][nt][r] = 0.f;

    const int NC = K / GKC;

#pragma unroll
    for (int c = 0; c < 3; c++)
        fill_stage(sbase + c * GSTAGE_B, Ah0 + c * GKC, Al0 + c * GKC,
                   Bh0 + c * GKC, Bl0 + c * GKC, K, tid);

    for (int c = 0; c < NC; c++) {
        const uint32_t stb = sbase + (c % 3) * GSTAGE_B;
        asm volatile("cp.async.wait_group %0;" :: "n"(2) : "memory");
        __syncthreads();

#pragma unroll
        for (int ks = 0; ks < 2; ks++) {
            const uint32_t ko = ks * 32;
            uint32_t ah[4][4], al[4][4], bh[2][4], bl[2][4];
#pragma unroll
            for (int mt = 0; mt < 4; mt++) {
                ldmx4(ah[mt], stb + 0 * GTILE_B + a_off[mt] + ko);
                ldmx4(al[mt], stb + 1 * GTILE_B + a_off[mt] + ko);
            }
#pragma unroll
            for (int np = 0; np < 2; np++) {
                ldmx4(bh[np], stb + 2 * GTILE_B + b_off[np] + ko);
                ldmx4(bl[np], stb + 3 * GTILE_B + b_off[np] + ko);
            }
#pragma unroll
            for (int mt = 0; mt < 4; mt++)
#pragma unroll
                for (int nt = 0; nt < 4; nt++) {
                    const int np = nt >> 1, bi = (nt & 1) * 2;
                    mma_bf16(acc[mt][nt], ah[mt], bh[np][bi], bh[np][bi + 1]);
                    mma_bf16(acc[mt][nt], al[mt], bh[np][bi], bh[np][bi + 1]);
                    mma_bf16(acc[mt][nt], ah[mt], bl[np][bi], bl[np][bi + 1]);
                }
        }

        __syncthreads();
        const int cn = c + 3;
        if (cn < NC)
            fill_stage(stb, Ah0 + cn * GKC, Al0 + cn * GKC,
                       Bh0 + cn * GKC, Bl0 + cn * GKC, K, tid);
    }

    const int rr = lane >> 2, cc = (lane & 3) * 2;
#pragma unroll
    for (int mt = 0; mt < 4; mt++) {
        const size_t mA = (size_t)(m0 + wm * 64 + mt * 16 + rr);
#pragma unroll
        for (int nt = 0; nt < 4; nt++) {
            const int n = n0 + wn * 32 + nt * 8 + cc;
            *(float2*)(C + mA * N + n) =
                make_float2(acc[mt][nt][0], acc[mt][nt][1]);
            *(float2*)(C + (mA + 8) * N + n) =
                make_float2(acc[mt][nt][2], acc[mt][nt][3]);
        }
    }
}

// ---------------------------------------------------------------------------
// RoPE tables (double precision)
// ---------------------------------------------------------------------------
__global__ void rope_tables_kernel()
{
    int idx = blockIdx.x * 256 + threadIdx.x;
    if (idx >= SEQ * (HDIM / 2)) return;
    int i = idx & 127;
    int pos = idx >> 7;
    double invf = pow(10000.0, -(double)(2 * i) / (double)HDIM);
    double ang = (double)pos * invf;
    g_cos[idx] = (float)cos(ang);
    g_sin[idx] = (float)sin(ang);
}

// ---------------------------------------------------------------------------
// RoPE apply + bf16 hi/lo split: X fp32 -> Xh/Xl bf16 (same layout)
// ---------------------------------------------------------------------------
__global__ void rope_split_kernel(const float* __restrict__ X,
                                  __nv_bfloat16* __restrict__ Xh,
                                  __nv_bfloat16* __restrict__ Xl, int heads)
{
    int idx = blockIdx.x * 256 + threadIdx.x;
    int total = MROWS * heads * (HDIM / 2);
    if (idx >= total) return;
    int i = idx & 127;
    int t = idx >> 7;
    int h = t % heads;
    int m = t / heads;
    int pos = m & (SEQ - 1);
    float c = g_cos[pos * 128 + i];
    float s = g_sin[pos * 128 + i];
    size_t base = (size_t)m * (heads * HDIM) + h * HDIM + i;
    float x1 = X[base];
    float x2 = X[base + 128];
    float y1 = x1 * c - x2 * s;
    float y2 = x2 * c + x1 * s;
    __nv_bfloat16 h1 = __float2bfloat16(y1);
    __nv_bfloat16 h2 = __float2bfloat16(y2);
    Xh[base]       = h1;
    Xh[base + 128] = h2;
    Xl[base]       = __float2bfloat16(y1 - __bfloat162float(h1));
    Xl[base + 128] = __float2bfloat16(y2 - __bfloat162float(h2));
}

// ---------------------------------------------------------------------------
// Tensor-core flash attention, bf16x3, no-max softmax (|logit| <= 50),
// FMA-pipe exp/rcp (zero MUFU in the hot path).
// CTA: 64 q-rows x one (b,h). 256 threads = 8 warps:
//   S phase:  warp (wq = wid&3, wn = wid>>2): 16q x 32k tile
//   PV phase: warp (wq, wd = wid>>2): 16q x 128d tile
// ---------------------------------------------------------------------------
#define DST 264   // Q/K smem row stride (bf16)
#define VST 72    // Vt smem row stride (bf16)
#define PST 72    // P smem row stride (bf16)
#define oQh 0
#define oQl 33792
#define oKh 67584
#define oKl 101376
#define oVh 135168
#define oVl 172032
#define oPh 208896
#define oPl 218112
#define oLrow 227328
#define ATTN_SMEM (227328 + 256)

__global__ void __launch_bounds__(256, 1)
attn_tc_kernel(const __nv_bfloat16* __restrict__ Qh, const __nv_bfloat16* __restrict__ Ql,
               const __nv_bfloat16* __restrict__ Kh, const __nv_bfloat16* __restrict__ Kl,
               const __nv_bfloat16* __restrict__ Vth, const __nv_bfloat16* __restrict__ Vtl,
               __nv_bfloat16* __restrict__ Ch, __nv_bfloat16* __restrict__ Cl)
{
    extern __shared__ char smraw[];
    const uint32_t sb = smem_u32(smraw);
    float* lrow = (float*)(smraw + oLrow);

    const int tid = threadIdx.x;
    const int wid = tid >> 5, lane = tid & 31;
    const int wq = wid & 3, wh = wid >> 2;     // wh: n-half (S) / d-half (PV)
    const int b  = blockIdx.y >> 4;
    const int h  = blockIdx.y & 15;
    const int kvh = h >> 1;
    const int q0 = blockIdx.x * 64;

    const char* gQh = (const char*)(Qh + ((size_t)(b * SEQ + q0)) * QCOLS + h * HDIM);
    const char* gQl = (const char*)(Ql + ((size_t)(b * SEQ + q0)) * QCOLS + h * HDIM);
    const char* gKh = (const char*)(Kh + ((size_t)(b * SEQ)) * KCOLS + kvh * HDIM);
    const char* gKl = (const char*)(Kl + ((size_t)(b * SEQ)) * KCOLS + kvh * HDIM);
    const char* gVh = (const char*)(Vth + ((size_t)(b * KCOLS + kvh * HDIM)) * SEQ);
    const char* gVl = (const char*)(Vtl + ((size_t)(b * KCOLS + kvh * HDIM)) * SEQ);

    if (tid < 64) lrow[tid] = 0.f;

    int klo = q0 - WINDOW;       if (klo < 0) klo = 0;
    int khi = q0 + 64 + WINDOW;  if (khi > SEQ) khi = SEQ;
    const int kt0 = klo >> 6;
    const int ntiles = (khi >> 6) - kt0;

    // ---- prologue loads: Q + K(0) [group], V(0) [group] ----
#pragma unroll
    for (int i = 0; i < 8; i++) {              // Q: 64 rows x 512B per split
        int id = tid + i * 256;
        int row = id >> 5, ch = id & 31;
        cp16(sb + oQh + row * (DST * 2) + ch * 16, gQh + (size_t)row * (QCOLS * 2) + ch * 16);
        cp16(sb + oQl + row * (DST * 2) + ch * 16, gQl + (size_t)row * (QCOLS * 2) + ch * 16);
    }
    {
        int kb = kt0 * 64;
#pragma unroll
        for (int i = 0; i < 8; i++) {          // K tile
            int id = tid + i * 256;
            int row = id >> 5, ch = id & 31;
            cp16(sb + oKh + row * (DST * 2) + ch * 16, gKh + (size_t)(kb + row) * (KCOLS * 2) + ch * 16);
            cp16(sb + oKl + row * (DST * 2) + ch * 16, gKl + (size_t)(kb + row) * (KCOLS * 2) + ch * 16);
        }
        asm volatile("cp.async.commit_group;" ::: "memory");
#pragma unroll
        for (int i = 0; i < 8; i++) {          // Vt tile: 256 rows x 128B
            int id = tid + i * 256;
            int row = id >> 3, ch = id & 7;
            cp16(sb + oVh + row * (VST * 2) + ch * 16, gVh + (size_t)row * (SEQ * 2) + kb * 2 + ch * 16);
            cp16(sb + oVl + row * (VST * 2) + ch * 16, gVl + (size_t)row * (SEQ * 2) + kb * 2 + ch * 16);
        }
        asm volatile("cp.async.commit_group;" ::: "memory");
    }
    asm volatile("cp.async.wait_group %0;" :: "n"(1) : "memory");
    __syncthreads();

    // fragment byte offsets
    const uint32_t a_off = ((wq * 16 + (lane & 15)) * DST + (lane >> 4) * 8) * 2;
    uint32_t bs_off[2];
#pragma unroll
    for (int np = 0; np < 2; np++)
        bs_off[np] = ((wh * 32 + np * 16 + (lane & 7) + ((lane >> 4) & 1) * 8) * DST
                      + ((lane >> 3) & 1) * 8) * 2;
    const uint32_t ap_off = ((wq * 16 + (lane & 15)) * PST + (lane >> 4) * 8) * 2;
    uint32_t bv_off[8];
#pragma unroll
    for (int np = 0; np < 8; np++)
        bv_off[np] = ((wh * 128 + np * 16 + (lane & 7) + ((lane >> 4) & 1) * 8) * VST
                      + ((lane >> 3) & 1) * 8) * 2;

    float oacc[16][4];
#pragma unroll
    for (int nt = 0; nt < 16; nt++)
#pragma unroll
        for (int r = 0; r < 4; r++) oacc[nt][r] = 0.f;

    const int r0 = wq * 16 + (lane >> 2), r1 = r0 + 8;
    const int qg0 = q0 + r0, qg1 = q0 + r1;

    for (int t = 0; t < ntiles; t++) {
        const int kbase = (kt0 + t) * 64;

        // ---- S = Q K^T (bf16x3) ----
        float sacc[4][4];
#pragma unroll
        for (int nt = 0; nt < 4; nt++)
#pragma unroll
            for (int r = 0; r < 4; r++) sacc[nt][r] = 0.f;

#pragma unroll 4
        for (int ks = 0; ks < 16; ks++) {
            const uint32_t ko = ks * 32;
            uint32_t qhf[4], qlf[4], khf[2][4], klf[2][4];
            ldmx4(qhf, sb + oQh + a_off + ko);
            ldmx4(qlf, sb + oQl + a_off + ko);
#pragma unroll
            for (int np = 0; np < 2; np++) {
                ldmx4(khf[np], sb + oKh + bs_off[np] + ko);
                ldmx4(klf[np], sb + oKl + bs_off[np] + ko);
            }
#pragma unroll
            for (int nt = 0; nt < 4; nt++) {
                const int np = nt >> 1, bi = (nt & 1) * 2;
                mma_bf16(sacc[nt], qhf, khf[np][bi], khf[np][bi + 1]);
                mma_bf16(sacc[nt], qlf, khf[np][bi], khf[np][bi + 1]);
                mma_bf16(sacc[nt], qhf, klf[np][bi], klf[np][bi + 1]);
            }
        }

        // ---- soft-cap + window mask + exp (FMA pipe), write P splits ----
        float psum0 = 0.f, psum1 = 0.f;
#pragma unroll
        for (int nt = 0; nt < 4; nt++) {
            const int cl = wh * 32 + nt * 8 + (lane & 3) * 2;
            const int cg = kbase + cl;
            float p[4];
#pragma unroll
            for (int e = 0; e < 4; e++) {
                const int qg = (e < 2) ? qg0 : qg1;
                const int kg = cg + (e & 1);
                int dlt = qg - kg; if (dlt < 0) dlt = -dlt;
                if (dlt <= WINDOW) {
                    float E = fexp(sacc[nt][e] * 0.0025f);       // e^{s/400}
                    float l = fmaf(-100.f, frcp(E + 1.f), 50.f); // 50*tanh(s/800)
                    p[e] = fexp(l);
                } else p[e] = 0.f;
            }
            psum0 += p[0] + p[1];
            psum1 += p[2] + p[3];
            __nv_bfloat16 h0 = __float2bfloat16(p[0]), h1 = __float2bfloat16(p[1]);
            __nv_bfloat16 h2 = __float2bfloat16(p[2]), h3 = __float2bfloat16(p[3]);
            *(__nv_bfloat162*)(smraw + oPh + (r0 * PST + cl) * 2) = __halves2bfloat162(h0, h1);
            *(__nv_bfloat162*)(smraw + oPh + (r1 * PST + cl) * 2) = __halves2bfloat162(h2, h3);
            *(__nv_bfloat162*)(smraw + oPl + (r0 * PST + cl) * 2) =
                __halves2bfloat162(__float2bfloat16(p[0] - __bfloat162float(h0)),
                                   __float2bfloat16(p[1] - __bfloat162float(h1)));
            *(__nv_bfloat162*)(smraw + oPl + (r1 * PST + cl) * 2) =
                __halves2bfloat162(__float2bfloat16(p[2] - __bfloat162float(h2)),
                                   __float2bfloat16(p[3] - __bfloat162float(h3)));
        }
        psum0 += __shfl_xor_sync(0xffffffffu, psum0, 1);
        psum0 += __shfl_xor_sync(0xffffffffu, psum0, 2);
        psum1 += __shfl_xor_sync(0xffffffffu, psum1, 1);
        psum1 += __shfl_xor_sync(0xffffffffu, psum1, 2);
        if ((lane & 3) == 0) {
            atomicAdd(&lrow[r0], psum0);
            atomicAdd(&lrow[r1], psum1);
        }

        // V(t) must be resident; K smem free after barrier
        asm volatile("cp.async.wait_group %0;" :: "n"(0) : "memory");
        __syncthreads();

        if (t + 1 < ntiles) {                 // prefetch K(t+1)
            int kb = kbase + 64;
#pragma unroll
            for (int i = 0; i < 8; i++) {
                int id = tid + i * 256;
                int row = id >> 5, ch = id & 31;
                cp16(sb + oKh + row * (DST * 2) + ch * 16, gKh + (size_t)(kb + row) * (KCOLS * 2) + ch * 16);
                cp16(sb + oKl + row * (DST * 2) + ch * 16, gKl + (size_t)(kb + row) * (KCOLS * 2) + ch * 16);
            }
            asm volatile("cp.async.commit_group;" ::: "memory");
        }

        // ---- O += P V (bf16x3) ----
#pragma unroll
        for (int kp = 0; kp < 4; kp++) {
            const uint32_t ko = kp * 32;
            uint32_t pah[4], pal[4];
            ldmx4(pah, sb + oPh + ap_off + ko);
            ldmx4(pal, sb + oPl + ap_off + ko);
#pragma unroll
            for (int np = 0; np < 8; np++) {
                uint32_t vbh[4], vbl[4];
                ldmx4(vbh, sb + oVh + bv_off[np] + ko);
                ldmx4(vbl, sb + oVl + bv_off[np] + ko);
#pragma unroll
                for (int i = 0; i < 2; i++) {
                    const int nt = np * 2 + i, bi = i * 2;
                    mma_bf16(oacc[nt], pah, vbh[bi], vbh[bi + 1]);
                    mma_bf16(oacc[nt], pal, vbh[bi], vbh[bi + 1]);
                    mma_bf16(oacc[nt], pah, vbl[bi], vbl[bi + 1]);
                }
            }
        }
        __syncthreads();                       // all warps done with V(t)

        if (t + 1 < ntiles) {                  // prefetch V(t+1)
            int kb = kbase + 64;
#pragma unroll
            for (int i = 0; i < 8; i++) {
                int id = tid + i * 256;
                int row = id >> 3, ch = id & 7;
                cp16(sb + oVh + row * (VST * 2) + ch * 16, gVh + (size_t)row * (SEQ * 2) + kb * 2 + ch * 16);
                cp16(sb + oVl + row * (VST * 2) + ch * 16, gVl + (size_t)row * (SEQ * 2) + kb * 2 + ch * 16);
            }
            asm volatile("cp.async.commit_group;" ::: "memory");
            asm volatile("cp.async.wait_group %0;" :: "n"(1) : "memory");   // K(t+1) ready
        }
        __syncthreads();
    }

    // ---- normalize, split to bf16 h/l, write context ----
    const float inv0 = 1.0f / lrow[r0];
    const float inv1 = 1.0f / lrow[r1];
    const size_t row0 = (size_t)(b * SEQ + q0 + r0) * QCOLS;
    const size_t row1 = (size_t)(b * SEQ + q0 + r1) * QCOLS;
#pragma unroll
    for (int nt = 0; nt < 16; nt++) {
        const int col = h * HDIM + wh * 128 + nt * 8 + (lane & 3) * 2;
        float v0 = oacc[nt][0] * inv0, v1 = oacc[nt][1] * inv0;
        float v2 = oacc[nt][2] * inv1, v3 = oacc[nt][3] * inv1;
        __nv_bfloat16 h0 = __float2bfloat16(v0), h1 = __float2bfloat16(v1);
        __nv_bfloat16 h2 = __float2bfloat16(v2), h3 = __float2bfloat16(v3);
        *(__nv_bfloat162*)(Ch + row0 + col) = __halves2bfloat162(h0, h1);
        *(__nv_bfloat162*)(Ch + row1 + col) = __halves2bfloat162(h2, h3);
        *(__nv_bfloat162*)(Cl + row0 + col) =
            __halves2bfloat162(__float2bfloat16(v0 - __bfloat162float(h0)),
                               __float2bfloat16(v1 - __bfloat162float(h1)));
        *(__nv_bfloat162*)(Cl + row1 + col) =
            __halves2bfloat162(__float2bfloat16(v2 - __bfloat162float(h2)),
                               __float2bfloat16(v3 - __bfloat162float(h3)));
    }
}

// ---------------------------------------------------------------------------
// launch
// ---------------------------------------------------------------------------
extern "C" void kernel_launch(void* const* d_in, const int* in_sizes, int n_in,
                              void* d_out, int out_size)
{
    const float* hid = (const float*)d_in[0];
    const float* Wq  = (const float*)d_in[1];
    const float* Wk  = (const float*)d_in[2];
    const float* Wv  = (const float*)d_in[3];
    const float* Wo  = (const float*)d_in[4];
    float* out = (float*)d_out;

    float *Qb, *Kb, *Vb;
    cudaGetSymbolAddress((void**)&Qb, g_Q);
    cudaGetSymbolAddress((void**)&Kb, g_K);
    cudaGetSymbolAddress((void**)&Vb, g_V);

    __nv_bfloat16 *Hh, *Hl, *WqtH, *WqtL, *WktH, *WktL, *WvtH, *WvtL, *WotH, *WotL;
    __nv_bfloat16 *Ch, *Cl, *Qh, *Ql, *Kh, *Kl, *VtH, *VtL;
    cudaGetSymbolAddress((void**)&Hh,   g_Hh);
    cudaGetSymbolAddress((void**)&Hl,   g_Hl);
    cudaGetSymbolAddress((void**)&WqtH, g_WqtH);
    cudaGetSymbolAddress((void**)&WqtL, g_WqtL);
    cudaGetSymbolAddress((void**)&WktH, g_WktH);
    cudaGetSymbolAddress((void**)&WktL, g_WktL);
    cudaGetSymbolAddress((void**)&WvtH, g_WvtH);
    cudaGetSymbolAddress((void**)&WvtL, g_WvtL);
    cudaGetSymbolAddress((void**)&WotH, g_WotH);
    cudaGetSymbolAddress((void**)&WotL, g_WotL);
    cudaGetSymbolAddress((void**)&Ch,   g_Ch);
    cudaGetSymbolAddress((void**)&Cl,   g_Cl);
    cudaGetSymbolAddress((void**)&Qh,   g_Qh);
    cudaGetSymbolAddress((void**)&Ql,   g_Ql);
    cudaGetSymbolAddress((void**)&Kh,   g_Kh);
    cudaGetSymbolAddress((void**)&Kl,   g_Kl);
    cudaGetSymbolAddress((void**)&VtH,  g_VtH);
    cudaGetSymbolAddress((void**)&VtL,  g_VtL);

    cudaFuncSetAttribute(gemm_mma_kernel, cudaFuncAttributeMaxDynamicSharedMemorySize,
                         GEMM_SMEM);
    cudaFuncSetAttribute(attn_tc_kernel, cudaFuncAttributeMaxDynamicSharedMemorySize,
                         ATTN_SMEM);

    rope_tables_kernel<<<(SEQ * 128 + 255) / 256, 256>>>();

    // splits / transposes of inputs
    split_kernel<<<(MROWS * EMBED / 4 + 255) / 256, 256>>>(hid, Hh, Hl, MROWS * EMBED / 4);
    tsplit_kernel<<<dim3(QCOLS / 32, EMBED / 32), dim3(32, 8)>>>(Wq, WqtH, WqtL, EMBED, QCOLS);
    tsplit_kernel<<<dim3(KCOLS / 32, EMBED / 32), dim3(32, 8)>>>(Wk, WktH, WktL, EMBED, KCOLS);
    tsplit_kernel<<<dim3(KCOLS / 32, EMBED / 32), dim3(32, 8)>>>(Wv, WvtH, WvtL, EMBED, KCOLS);
    tsplit_kernel<<<dim3(EMBED / 32, QCOLS / 32), dim3(32, 8)>>>(Wo, WotH, WotL, QCOLS, EMBED);

    // projections (mma.sync bf16x3)
    gemm_mma_kernel<<<dim3(QCOLS / 128, MROWS / 128), 256, GEMM_SMEM>>>(
        Hh, Hl, WqtH, WqtL, Qb, MROWS, QCOLS, EMBED);
    gemm_mma_kernel<<<dim3(KCOLS / 128, MROWS / 128), 256, GEMM_SMEM>>>(
        Hh, Hl, WktH, WktL, Kb, MROWS, KCOLS, EMBED);
    gemm_mma_kernel<<<dim3(KCOLS / 128, MROWS / 128), 256, GEMM_SMEM>>>(
        Hh, Hl, WvtH, WvtL, Vb, MROWS, KCOLS, EMBED);

    // RoPE + split to bf16 attention operands; V transpose+split
    rope_split_kernel<<<(MROWS * NH  * 128 + 255) / 256, 256>>>(Qb, Qh, Ql, NH);
    rope_split_kernel<<<(MROWS * NKV * 128 + 255) / 256, 256>>>(Kb, Kh, Kl, NKV);
    vtsplit_kernel<<<dim3(SEQ / 32, KCOLS / 32, BATCH), dim3(32, 8)>>>(Vb, VtH, VtL);

    // tensor-core attention -> Ch/Cl bf16 splits
    attn_tc_kernel<<<dim3(SEQ / 64, BATCH * NH), 256, ATTN_SMEM>>>(
        Qh, Ql, Kh, Kl, VtH, VtL, Ch, Cl);

    // output projection straight into d_out
    gemm_mma_kernel<<<dim3(EMBED / 128, MROWS / 128), 256, GEMM_SMEM>>>(
        Ch, Cl, WotH, WotL, out, MROWS, EMBED, QCOLS);
}

// round 9
// speedup vs baseline: 2.4048x; 1.1248x over previous
#include <cuda_runtime.h>
#include <cuda_bf16.h>
#include <math.h>
#include <stdint.h>

// ---------------------------------------------------------------------------
// Problem constants
// ---------------------------------------------------------------------------
#define BATCH   2
#define SEQ     2048
#define EMBED   3584
#define NH      16
#define NKV     8
#define HDIM    256
#define MROWS   (BATCH*SEQ)          // 4096
#define QCOLS   (NH*HDIM)            // 4096
#define KCOLS   (NKV*HDIM)           // 2048
#define WINDOW  1024

// ---------------------------------------------------------------------------
// Static device scratch (no cudaMalloc allowed)
// ---------------------------------------------------------------------------
__device__ float g_Q  [(size_t)MROWS*QCOLS];
__device__ float g_K  [(size_t)MROWS*KCOLS];
__device__ float g_V  [(size_t)MROWS*KCOLS];
__device__ float g_cos[SEQ*(HDIM/2)];
__device__ float g_sin[SEQ*(HDIM/2)];

// bf16 hi/lo splits
__device__ __nv_bfloat16 g_Hh  [(size_t)MROWS*EMBED];
__device__ __nv_bfloat16 g_Hl  [(size_t)MROWS*EMBED];
__device__ __nv_bfloat16 g_WqtH[(size_t)QCOLS*EMBED];
__device__ __nv_bfloat16 g_WqtL[(size_t)QCOLS*EMBED];
__device__ __nv_bfloat16 g_WktH[(size_t)KCOLS*EMBED];
__device__ __nv_bfloat16 g_WktL[(size_t)KCOLS*EMBED];
__device__ __nv_bfloat16 g_WvtH[(size_t)KCOLS*EMBED];
__device__ __nv_bfloat16 g_WvtL[(size_t)KCOLS*EMBED];
__device__ __nv_bfloat16 g_WotH[(size_t)EMBED*QCOLS];
__device__ __nv_bfloat16 g_WotL[(size_t)EMBED*QCOLS];
__device__ __nv_bfloat16 g_Ch  [(size_t)MROWS*QCOLS];
__device__ __nv_bfloat16 g_Cl  [(size_t)MROWS*QCOLS];

// attention operands (bf16 splits)
__device__ __nv_bfloat16 g_Qh [(size_t)MROWS*QCOLS];
__device__ __nv_bfloat16 g_Ql [(size_t)MROWS*QCOLS];
__device__ __nv_bfloat16 g_Kh [(size_t)MROWS*KCOLS];
__device__ __nv_bfloat16 g_Kl [(size_t)MROWS*KCOLS];
__device__ __nv_bfloat16 g_VtH[(size_t)MROWS*KCOLS];   // per-batch transposed [KCOLS][SEQ]
__device__ __nv_bfloat16 g_VtL[(size_t)MROWS*KCOLS];

// ---------------------------------------------------------------------------
// PTX helpers (sm_100-safe: no tcgen05, no clusters)
// ---------------------------------------------------------------------------
__device__ __forceinline__ uint32_t smem_u32(const void* p) {
    uint32_t a;
    asm("{ .reg .u64 t; cvta.to.shared.u64 t, %1; cvt.u32.u64 %0, t; }" : "=r"(a) : "l"(p));
    return a;
}
__device__ __forceinline__ void cp16(uint32_t dst, const void* src) {
    asm volatile("cp.async.cg.shared.global [%0], [%1], 16;" :: "r"(dst), "l"(src) : "memory");
}
__device__ __forceinline__ void ldmx4(uint32_t* r, uint32_t addr) {
    asm volatile("ldmatrix.sync.aligned.m8n8.x4.shared.b16 {%0,%1,%2,%3}, [%4];"
                 : "=r"(r[0]), "=r"(r[1]), "=r"(r[2]), "=r"(r[3]) : "r"(addr));
}
__device__ __forceinline__ void mma_bf16(float* c, const uint32_t* a,
                                         uint32_t b0, uint32_t b1) {
    asm volatile(
        "mma.sync.aligned.m16n8k16.row.col.f32.bf16.bf16.f32 "
        "{%0,%1,%2,%3}, {%4,%5,%6,%7}, {%8,%9}, {%0,%1,%2,%3};"
        : "+f"(c[0]), "+f"(c[1]), "+f"(c[2]), "+f"(c[3])
        : "r"(a[0]), "r"(a[1]), "r"(a[2]), "r"(a[3]), "r"(b0), "r"(b1));
}

// FMA-pipe exp (no MUFU): e^x for |x| <= ~85, rel err ~1.5e-7
__device__ __forceinline__ float fexp(float x) {
    float y  = x * 1.4426950408889634f;          // log2(e)
    float fm = y + 12582912.0f;                  // round-to-nearest via magic
    float nf = fm - 12582912.0f;
    float f  = y - nf;                           // [-0.5, 0.5]
    int   sc = ((__float_as_int(fm) - 0x4B400000) + 127) << 23;
    float t  = f * 0.6931471805599453f;
    float p  = 1.0f + t*(1.0f + t*(0.5f + t*(0.16666667f +
               t*(0.041666667f + t*(0.008333334f + t*0.0013888889f)))));
    return p * __int_as_float(sc);
}
// FMA-pipe reciprocal (bit-hack + 3 Newton), rel err ~1e-10 for d in [1,4]
__device__ __forceinline__ float frcp(float d) {
    float r = __int_as_float(0x7EF311C3 - __float_as_int(d));
    r = r * (2.0f - d * r);
    r = r * (2.0f - d * r);
    r = r * (2.0f - d * r);
    return r;
}

// ---------------------------------------------------------------------------
// fp32 -> bf16 hi/lo split (vectorized)
// ---------------------------------------------------------------------------
__global__ void split_kernel(const float* __restrict__ in,
                             __nv_bfloat16* __restrict__ hi,
                             __nv_bfloat16* __restrict__ lo, int n4)
{
    int i = blockIdx.x * 256 + threadIdx.x;
    if (i >= n4) return;
    float4 v = ((const float4*)in)[i];
    __nv_bfloat16 h0 = __float2bfloat16(v.x);
    __nv_bfloat16 h1 = __float2bfloat16(v.y);
    __nv_bfloat16 h2 = __float2bfloat16(v.z);
    __nv_bfloat16 h3 = __float2bfloat16(v.w);
    __nv_bfloat16 l0 = __float2bfloat16(v.x - __bfloat162float(h0));
    __nv_bfloat16 l1 = __float2bfloat16(v.y - __bfloat162float(h1));
    __nv_bfloat16 l2 = __float2bfloat16(v.z - __bfloat162float(h2));
    __nv_bfloat16 l3 = __float2bfloat16(v.w - __bfloat162float(h3));
    ((__nv_bfloat162*)hi)[2*i]   = __halves2bfloat162(h0, h1);
    ((__nv_bfloat162*)hi)[2*i+1] = __halves2bfloat162(h2, h3);
    ((__nv_bfloat162*)lo)[2*i]   = __halves2bfloat162(l0, l1);
    ((__nv_bfloat162*)lo)[2*i+1] = __halves2bfloat162(l2, l3);
}

// ---------------------------------------------------------------------------
// Transpose + split: W [K,N] fp32 -> Th/Tl [N,K] bf16
// ---------------------------------------------------------------------------
__global__ void tsplit_kernel(const float* __restrict__ W,
                              __nv_bfloat16* __restrict__ Th,
                              __nv_bfloat16* __restrict__ Tl, int K, int N)
{
    __shared__ float t[32][33];
    int n0 = blockIdx.x * 32, k0 = blockIdx.y * 32;
    int tx = threadIdx.x, ty = threadIdx.y;
#pragma unroll
    for (int i = 0; i < 32; i += 8)
        t[ty + i][tx] = W[(size_t)(k0 + ty + i) * N + n0 + tx];
    __syncthreads();
#pragma unroll
    for (int i = 0; i < 32; i += 8) {
        float v = t[tx][ty + i];
        __nv_bfloat16 h = __float2bfloat16(v);
        __nv_bfloat16 l = __float2bfloat16(v - __bfloat162float(h));
        size_t o = (size_t)(n0 + ty + i) * K + k0 + tx;
        Th[o] = h;
        Tl[o] = l;
    }
}

// ---------------------------------------------------------------------------
// V transpose+split per batch: g_V [b*SEQ+s][KCOLS] -> Vt [b][KCOLS][SEQ]
// ---------------------------------------------------------------------------
__global__ void vtsplit_kernel(const float* __restrict__ V,
                               __nv_bfloat16* __restrict__ Th,
                               __nv_bfloat16* __restrict__ Tl)
{
    __shared__ float t[32][33];
    int s0 = blockIdx.x * 32, c0 = blockIdx.y * 32, b = blockIdx.z;
    int tx = threadIdx.x, ty = threadIdx.y;
#pragma unroll
    for (int i = 0; i < 32; i += 8)
        t[ty + i][tx] = V[((size_t)b * SEQ + s0 + ty + i) * KCOLS + c0 + tx];
    __syncthreads();
#pragma unroll
    for (int i = 0; i < 32; i += 8) {
        float v = t[tx][ty + i];
        __nv_bfloat16 h = __float2bfloat16(v);
        __nv_bfloat16 l = __float2bfloat16(v - __bfloat162float(h));
        size_t o = ((size_t)b * KCOLS + c0 + ty + i) * SEQ + s0 + tx;
        Th[o] = h;
        Tl[o] = l;
    }
}

// ---------------------------------------------------------------------------
// mma.sync bf16x3 GEMM v2: 2-stage pipeline, 2 CTAs/SM, term-ordered MMAs
// C[M,N] fp32 = (Ah+Al)[M,K] @ (Bh+Bl)[N,K]^T
// ---------------------------------------------------------------------------
#define GKC       32
#define GSTRIDE   40
#define GTILE_B   (128*GSTRIDE*2)    // 10240 B per tile
#define GSTAGE_B  (4*GTILE_B)        // Ah, Al, Bh, Bl = 40960 B
#define GEMM_SMEM (2*GSTAGE_B)       // 81920 B -> 2 CTAs/SM

__device__ __forceinline__ void fill_stage(uint32_t stb,
                                           const __nv_bfloat16* Ah0,
                                           const __nv_bfloat16* Al0,
                                           const __nv_bfloat16* Bh0,
                                           const __nv_bfloat16* Bl0,
                                           int K, int tid)
{
    const __nv_bfloat16* srcs[4] = {Ah0, Al0, Bh0, Bl0};
#pragma unroll
    for (int t = 0; t < 4; t++) {
        uint32_t tb = stb + t * GTILE_B;
        const char* s = (const char*)srcs[t];
#pragma unroll
        for (int i = 0; i < 2; i++) {
            int id = tid + i * 256;
            int row = id >> 2, ch = id & 3;
            cp16(tb + row * (GSTRIDE * 2) + ch * 16,
                 s + (size_t)row * K * 2 + ch * 16);
        }
    }
    asm volatile("cp.async.commit_group;" ::: "memory");
}

__global__ void __launch_bounds__(256, 2)
gemm_mma_kernel(const __nv_bfloat16* __restrict__ Ah,
                const __nv_bfloat16* __restrict__ Al,
                const __nv_bfloat16* __restrict__ Bh,
                const __nv_bfloat16* __restrict__ Bl,
                float* __restrict__ C, int M, int N, int K)
{
    extern __shared__ char gsm[];
    const uint32_t sbase = smem_u32(gsm);
    const int tid = threadIdx.x;
    const int wid = tid >> 5, lane = tid & 31;
    const int wm = wid & 1, wn = wid >> 1;
    const int m0 = blockIdx.y * 128, n0 = blockIdx.x * 128;

    uint32_t a_off[4], b_off[2];
#pragma unroll
    for (int mt = 0; mt < 4; mt++)
        a_off[mt] = ((wm * 64 + mt * 16 + (lane & 15)) * GSTRIDE
                     + (lane >> 4) * 8) * 2;
#pragma unroll
    for (int np = 0; np < 2; np++)
        b_off[np] = ((wn * 32 + np * 16 + (lane & 7) + ((lane >> 4) & 1) * 8) * GSTRIDE
                     + ((lane >> 3) & 1) * 8) * 2;

    const __nv_bfloat16* Ah0 = Ah + (size_t)m0 * K;
    const __nv_bfloat16* Al0 = Al + (size_t)m0 * K;
    const __nv_bfloat16* Bh0 = Bh + (size_t)n0 * K;
    const __nv_bfloat16* Bl0 = Bl + (size_t)n0 * K;

    float acc[4][4][4];
#pragma unroll
    for (int mt = 0; mt < 4; mt++)
#pragma unroll
        for (int nt = 0; nt < 4; nt++)
#pragma unroll
            for (int r = 0; r < 4; r++) acc[mt][nt][r] = 0.f;

    const int NC = K / GKC;

    // prologue: 2 stages in flight
#pragma unroll
    for (int c = 0; c < 2; c++)
        fill_stage(sbase + c * GSTAGE_B, Ah0 + c * GKC, Al0 + c * GKC,
                   Bh0 + c * GKC, Bl0 + c * GKC, K, tid);

    for (int c = 0; c < NC; c++) {
        const uint32_t stb = sbase + (c & 1) * GSTAGE_B;
        asm volatile("cp.async.wait_group %0;" :: "n"(1) : "memory");
        __syncthreads();

#pragma unroll
        for (int ks = 0; ks < 2; ks++) {
            const uint32_t ko = ks * 32;
            uint32_t ax[4][4], bx[2][4];

            // ---- term 1: Ah * Bh ----
#pragma unroll
            for (int mt = 0; mt < 4; mt++) ldmx4(ax[mt], stb + 0 * GTILE_B + a_off[mt] + ko);
#pragma unroll
            for (int np = 0; np < 2; np++) ldmx4(bx[np], stb + 2 * GTILE_B + b_off[np] + ko);
#pragma unroll
            for (int mt = 0; mt < 4; mt++)
#pragma unroll
                for (int nt = 0; nt < 4; nt++) {
                    const int np = nt >> 1, bi = (nt & 1) * 2;
                    mma_bf16(acc[mt][nt], ax[mt], bx[np][bi], bx[np][bi + 1]);
                }

            // ---- term 2: Al * Bh (reuse Bh frags) ----
#pragma unroll
            for (int mt = 0; mt < 4; mt++) ldmx4(ax[mt], stb + 1 * GTILE_B + a_off[mt] + ko);
#pragma unroll
            for (int mt = 0; mt < 4; mt++)
#pragma unroll
                for (int nt = 0; nt < 4; nt++) {
                    const int np = nt >> 1, bi = (nt & 1) * 2;
                    mma_bf16(acc[mt][nt], ax[mt], bx[np][bi], bx[np][bi + 1]);
                }

            // ---- term 3: Ah * Bl (reload Ah, load Bl) ----
#pragma unroll
            for (int mt = 0; mt < 4; mt++) ldmx4(ax[mt], stb + 0 * GTILE_B + a_off[mt] + ko);
#pragma unroll
            for (int np = 0; np < 2; np++) ldmx4(bx[np], stb + 3 * GTILE_B + b_off[np] + ko);
#pragma unroll
            for (int mt = 0; mt < 4; mt++)
#pragma unroll
                for (int nt = 0; nt < 4; nt++) {
                    const int np = nt >> 1, bi = (nt & 1) * 2;
                    mma_bf16(acc[mt][nt], ax[mt], bx[np][bi], bx[np][bi + 1]);
                }
        }

        __syncthreads();
        const int cn = c + 2;
        if (cn < NC)
            fill_stage(stb, Ah0 + cn * GKC, Al0 + cn * GKC,
                       Bh0 + cn * GKC, Bl0 + cn * GKC, K, tid);
    }

    const int rr = lane >> 2, cc = (lane & 3) * 2;
#pragma unroll
    for (int mt = 0; mt < 4; mt++) {
        const size_t mA = (size_t)(m0 + wm * 64 + mt * 16 + rr);
#pragma unroll
        for (int nt = 0; nt < 4; nt++) {
            const int n = n0 + wn * 32 + nt * 8 + cc;
            *(float2*)(C + mA * N + n) =
                make_float2(acc[mt][nt][0], acc[mt][nt][1]);
            *(float2*)(C + (mA + 8) * N + n) =
                make_float2(acc[mt][nt][2], acc[mt][nt][3]);
        }
    }
}

// ---------------------------------------------------------------------------
// RoPE tables (double precision)
// ---------------------------------------------------------------------------
__global__ void rope_tables_kernel()
{
    int idx = blockIdx.x * 256 + threadIdx.x;
    if (idx >= SEQ * (HDIM / 2)) return;
    int i = idx & 127;
    int pos = idx >> 7;
    double invf = pow(10000.0, -(double)(2 * i) / (double)HDIM);
    double ang = (double)pos * invf;
    g_cos[idx] = (float)cos(ang);
    g_sin[idx] = (float)sin(ang);
}

// ---------------------------------------------------------------------------
// RoPE apply + bf16 hi/lo split: X fp32 -> Xh/Xl bf16 (same layout)
// ---------------------------------------------------------------------------
__global__ void rope_split_kernel(const float* __restrict__ X,
                                  __nv_bfloat16* __restrict__ Xh,
                                  __nv_bfloat16* __restrict__ Xl, int heads)
{
    int idx = blockIdx.x * 256 + threadIdx.x;
    int total = MROWS * heads * (HDIM / 2);
    if (idx >= total) return;
    int i = idx & 127;
    int t = idx >> 7;
    int h = t % heads;
    int m = t / heads;
    int pos = m & (SEQ - 1);
    float c = g_cos[pos * 128 + i];
    float s = g_sin[pos * 128 + i];
    size_t base = (size_t)m * (heads * HDIM) + h * HDIM + i;
    float x1 = X[base];
    float x2 = X[base + 128];
    float y1 = x1 * c - x2 * s;
    float y2 = x2 * c + x1 * s;
    __nv_bfloat16 h1 = __float2bfloat16(y1);
    __nv_bfloat16 h2 = __float2bfloat16(y2);
    Xh[base]       = h1;
    Xh[base + 128] = h2;
    Xl[base]       = __float2bfloat16(y1 - __bfloat162float(h1));
    Xl[base + 128] = __float2bfloat16(y2 - __bfloat162float(h2));
}

// ---------------------------------------------------------------------------
// Tensor-core flash attention, bf16x3, no-max softmax (|logit| <= 50),
// FMA-pipe exp/rcp (zero MUFU in the hot path).
// CTA: 64 q-rows x one (b,h). 256 threads = 8 warps:
//   S phase:  warp (wq = wid&3, wn = wid>>2): 16q x 32k tile
//   PV phase: warp (wq, wd = wid>>2): 16q x 128d tile
// ---------------------------------------------------------------------------
#define DST 264   // Q/K smem row stride (bf16)
#define VST 72    // Vt smem row stride (bf16)
#define PST 72    // P smem row stride (bf16)
#define oQh 0
#define oQl 33792
#define oKh 67584
#define oKl 101376
#define oVh 135168
#define oVl 172032
#define oPh 208896
#define oPl 218112
#define oLrow 227328
#define ATTN_SMEM (227328 + 256)

__global__ void __launch_bounds__(256, 1)
attn_tc_kernel(const __nv_bfloat16* __restrict__ Qh, const __nv_bfloat16* __restrict__ Ql,
               const __nv_bfloat16* __restrict__ Kh, const __nv_bfloat16* __restrict__ Kl,
               const __nv_bfloat16* __restrict__ Vth, const __nv_bfloat16* __restrict__ Vtl,
               __nv_bfloat16* __restrict__ Ch, __nv_bfloat16* __restrict__ Cl)
{
    extern __shared__ char smraw[];
    const uint32_t sb = smem_u32(smraw);
    float* lrow = (float*)(smraw + oLrow);

    const int tid = threadIdx.x;
    const int wid = tid >> 5, lane = tid & 31;
    const int wq = wid & 3, wh = wid >> 2;     // wh: n-half (S) / d-half (PV)
    const int b  = blockIdx.y >> 4;
    const int h  = blockIdx.y & 15;
    const int kvh = h >> 1;
    const int q0 = blockIdx.x * 64;

    const char* gQh = (const char*)(Qh + ((size_t)(b * SEQ + q0)) * QCOLS + h * HDIM);
    const char* gQl = (const char*)(Ql + ((size_t)(b * SEQ + q0)) * QCOLS + h * HDIM);
    const char* gKh = (const char*)(Kh + ((size_t)(b * SEQ)) * KCOLS + kvh * HDIM);
    const char* gKl = (const char*)(Kl + ((size_t)(b * SEQ)) * KCOLS + kvh * HDIM);
    const char* gVh = (const char*)(Vth + ((size_t)(b * KCOLS + kvh * HDIM)) * SEQ);
    const char* gVl = (const char*)(Vtl + ((size_t)(b * KCOLS + kvh * HDIM)) * SEQ);

    if (tid < 64) lrow[tid] = 0.f;

    int klo = q0 - WINDOW;       if (klo < 0) klo = 0;
    int khi = q0 + 64 + WINDOW;  if (khi > SEQ) khi = SEQ;
    const int kt0 = klo >> 6;
    const int ntiles = (khi >> 6) - kt0;

    // ---- prologue loads: Q + K(0) [group], V(0) [group] ----
#pragma unroll
    for (int i = 0; i < 8; i++) {              // Q: 64 rows x 512B per split
        int id = tid + i * 256;
        int row = id >> 5, ch = id & 31;
        cp16(sb + oQh + row * (DST * 2) + ch * 16, gQh + (size_t)row * (QCOLS * 2) + ch * 16);
        cp16(sb + oQl + row * (DST * 2) + ch * 16, gQl + (size_t)row * (QCOLS * 2) + ch * 16);
    }
    {
        int kb = kt0 * 64;
#pragma unroll
        for (int i = 0; i < 8; i++) {          // K tile
            int id = tid + i * 256;
            int row = id >> 5, ch = id & 31;
            cp16(sb + oKh + row * (DST * 2) + ch * 16, gKh + (size_t)(kb + row) * (KCOLS * 2) + ch * 16);
            cp16(sb + oKl + row * (DST * 2) + ch * 16, gKl + (size_t)(kb + row) * (KCOLS * 2) + ch * 16);
        }
        asm volatile("cp.async.commit_group;" ::: "memory");
#pragma unroll
        for (int i = 0; i < 8; i++) {          // Vt tile: 256 rows x 128B
            int id = tid + i * 256;
            int row = id >> 3, ch = id & 7;
            cp16(sb + oVh + row * (VST * 2) + ch * 16, gVh + (size_t)row * (SEQ * 2) + kb * 2 + ch * 16);
            cp16(sb + oVl + row * (VST * 2) + ch * 16, gVl + (size_t)row * (SEQ * 2) + kb * 2 + ch * 16);
        }
        asm volatile("cp.async.commit_group;" ::: "memory");
    }
    asm volatile("cp.async.wait_group %0;" :: "n"(1) : "memory");
    __syncthreads();

    // fragment byte offsets
    const uint32_t a_off = ((wq * 16 + (lane & 15)) * DST + (lane >> 4) * 8) * 2;
    uint32_t bs_off[2];
#pragma unroll
    for (int np = 0; np < 2; np++)
        bs_off[np] = ((wh * 32 + np * 16 + (lane & 7) + ((lane >> 4) & 1) * 8) * DST
                      + ((lane >> 3) & 1) * 8) * 2;
    const uint32_t ap_off = ((wq * 16 + (lane & 15)) * PST + (lane >> 4) * 8) * 2;
    uint32_t bv_off[8];
#pragma unroll
    for (int np = 0; np < 8; np++)
        bv_off[np] = ((wh * 128 + np * 16 + (lane & 7) + ((lane >> 4) & 1) * 8) * VST
                      + ((lane >> 3) & 1) * 8) * 2;

    float oacc[16][4];
#pragma unroll
    for (int nt = 0; nt < 16; nt++)
#pragma unroll
        for (int r = 0; r < 4; r++) oacc[nt][r] = 0.f;

    const int r0 = wq * 16 + (lane >> 2), r1 = r0 + 8;
    const int qg0 = q0 + r0, qg1 = q0 + r1;

    for (int t = 0; t < ntiles; t++) {
        const int kbase = (kt0 + t) * 64;

        // ---- S = Q K^T (bf16x3) ----
        float sacc[4][4];
#pragma unroll
        for (int nt = 0; nt < 4; nt++)
#pragma unroll
            for (int r = 0; r < 4; r++) sacc[nt][r] = 0.f;

#pragma unroll 4
        for (int ks = 0; ks < 16; ks++) {
            const uint32_t ko = ks * 32;
            uint32_t qhf[4], qlf[4], khf[2][4], klf[2][4];
            ldmx4(qhf, sb + oQh + a_off + ko);
            ldmx4(qlf, sb + oQl + a_off + ko);
#pragma unroll
            for (int np = 0; np < 2; np++) {
                ldmx4(khf[np], sb + oKh + bs_off[np] + ko);
                ldmx4(klf[np], sb + oKl + bs_off[np] + ko);
            }
#pragma unroll
            for (int nt = 0; nt < 4; nt++) {
                const int np = nt >> 1, bi = (nt & 1) * 2;
                mma_bf16(sacc[nt], qhf, khf[np][bi], khf[np][bi + 1]);
                mma_bf16(sacc[nt], qlf, khf[np][bi], khf[np][bi + 1]);
                mma_bf16(sacc[nt], qhf, klf[np][bi], klf[np][bi + 1]);
            }
        }

        // ---- soft-cap + window mask + exp (FMA pipe), write P splits ----
        float psum0 = 0.f, psum1 = 0.f;
#pragma unroll
        for (int nt = 0; nt < 4; nt++) {
            const int cl = wh * 32 + nt * 8 + (lane & 3) * 2;
            const int cg = kbase + cl;
            float p[4];
#pragma unroll
            for (int e = 0; e < 4; e++) {
                const int qg = (e < 2) ? qg0 : qg1;
                const int kg = cg + (e & 1);
                int dlt = qg - kg; if (dlt < 0) dlt = -dlt;
                if (dlt <= WINDOW) {
                    float E = fexp(sacc[nt][e] * 0.0025f);       // e^{s/400}
                    float l = fmaf(-100.f, frcp(E + 1.f), 50.f); // 50*tanh(s/800)
                    p[e] = fexp(l);
                } else p[e] = 0.f;
            }
            psum0 += p[0] + p[1];
            psum1 += p[2] + p[3];
            __nv_bfloat16 h0 = __float2bfloat16(p[0]), h1 = __float2bfloat16(p[1]);
            __nv_bfloat16 h2 = __float2bfloat16(p[2]), h3 = __float2bfloat16(p[3]);
            *(__nv_bfloat162*)(smraw + oPh + (r0 * PST + cl) * 2) = __halves2bfloat162(h0, h1);
            *(__nv_bfloat162*)(smraw + oPh + (r1 * PST + cl) * 2) = __halves2bfloat162(h2, h3);
            *(__nv_bfloat162*)(smraw + oPl + (r0 * PST + cl) * 2) =
                __halves2bfloat162(__float2bfloat16(p[0] - __bfloat162float(h0)),
                                   __float2bfloat16(p[1] - __bfloat162float(h1)));
            *(__nv_bfloat162*)(smraw + oPl + (r1 * PST + cl) * 2) =
                __halves2bfloat162(__float2bfloat16(p[2] - __bfloat162float(h2)),
                                   __float2bfloat16(p[3] - __bfloat162float(h3)));
        }
        psum0 += __shfl_xor_sync(0xffffffffu, psum0, 1);
        psum0 += __shfl_xor_sync(0xffffffffu, psum0, 2);
        psum1 += __shfl_xor_sync(0xffffffffu, psum1, 1);
        psum1 += __shfl_xor_sync(0xffffffffu, psum1, 2);
        if ((lane & 3) == 0) {
            atomicAdd(&lrow[r0], psum0);
            atomicAdd(&lrow[r1], psum1);
        }

        // V(t) must be resident; K smem free after barrier
        asm volatile("cp.async.wait_group %0;" :: "n"(0) : "memory");
        __syncthreads();

        if (t + 1 < ntiles) {                 // prefetch K(t+1)
            int kb = kbase + 64;
#pragma unroll
            for (int i = 0; i < 8; i++) {
                int id = tid + i * 256;
                int row = id >> 5, ch = id & 31;
                cp16(sb + oKh + row * (DST * 2) + ch * 16, gKh + (size_t)(kb + row) * (KCOLS * 2) + ch * 16);
                cp16(sb + oKl + row * (DST * 2) + ch * 16, gKl + (size_t)(kb + row) * (KCOLS * 2) + ch * 16);
            }
            asm volatile("cp.async.commit_group;" ::: "memory");
        }

        // ---- O += P V (bf16x3) ----
#pragma unroll
        for (int kp = 0; kp < 4; kp++) {
            const uint32_t ko = kp * 32;
            uint32_t pah[4], pal[4];
            ldmx4(pah, sb + oPh + ap_off + ko);
            ldmx4(pal, sb + oPl + ap_off + ko);
#pragma unroll
            for (int np = 0; np < 8; np++) {
                uint32_t vbh[4], vbl[4];
                ldmx4(vbh, sb + oVh + bv_off[np] + ko);
                ldmx4(vbl, sb + oVl + bv_off[np] + ko);
#pragma unroll
                for (int i = 0; i < 2; i++) {
                    const int nt = np * 2 + i, bi = i * 2;
                    mma_bf16(oacc[nt], pah, vbh[bi], vbh[bi + 1]);
                    mma_bf16(oacc[nt], pal, vbh[bi], vbh[bi + 1]);
                    mma_bf16(oacc[nt], pah, vbl[bi], vbl[bi + 1]);
                }
            }
        }
        __syncthreads();                       // all warps done with V(t)

        if (t + 1 < ntiles) {                  // prefetch V(t+1)
            int kb = kbase + 64;
#pragma unroll
            for (int i = 0; i < 8; i++) {
                int id = tid + i * 256;
                int row = id >> 3, ch = id & 7;
                cp16(sb + oVh + row * (VST * 2) + ch * 16, gVh + (size_t)row * (SEQ * 2) + kb * 2 + ch * 16);
                cp16(sb + oVl + row * (VST * 2) + ch * 16, gVl + (size_t)row * (SEQ * 2) + kb * 2 + ch * 16);
            }
            asm volatile("cp.async.commit_group;" ::: "memory");
            asm volatile("cp.async.wait_group %0;" :: "n"(1) : "memory");   // K(t+1) ready
        }
        __syncthreads();
    }

    // ---- normalize, split to bf16 h/l, write context ----
    const float inv0 = 1.0f / lrow[r0];
    const float inv1 = 1.0f / lrow[r1];
    const size_t row0 = (size_t)(b * SEQ + q0 + r0) * QCOLS;
    const size_t row1 = (size_t)(b * SEQ + q0 + r1) * QCOLS;
#pragma unroll
    for (int nt = 0; nt < 16; nt++) {
        const int col = h * HDIM + wh * 128 + nt * 8 + (lane & 3) * 2;
        float v0 = oacc[nt][0] * inv0, v1 = oacc[nt][1] * inv0;
        float v2 = oacc[nt][2] * inv1, v3 = oacc[nt][3] * inv1;
        __nv_bfloat16 h0 = __float2bfloat16(v0), h1 = __float2bfloat16(v1);
        __nv_bfloat16 h2 = __float2bfloat16(v2), h3 = __float2bfloat16(v3);
        *(__nv_bfloat162*)(Ch + row0 + col) = __halves2bfloat162(h0, h1);
        *(__nv_bfloat162*)(Ch + row1 + col) = __halves2bfloat162(h2, h3);
        *(__nv_bfloat162*)(Cl + row0 + col) =
            __halves2bfloat162(__float2bfloat16(v0 - __bfloat162float(h0)),
                               __float2bfloat16(v1 - __bfloat162float(h1)));
        *(__nv_bfloat162*)(Cl + row1 + col) =
            __halves2bfloat162(__float2bfloat16(v2 - __bfloat162float(h2)),
                               __float2bfloat16(v3 - __bfloat162float(h3)));
    }
}

// ---------------------------------------------------------------------------
// launch
// ---------------------------------------------------------------------------
extern "C" void kernel_launch(void* const* d_in, const int* in_sizes, int n_in,
                              void* d_out, int out_size)
{
    const float* hid = (const float*)d_in[0];
    const float* Wq  = (const float*)d_in[1];
    const float* Wk  = (const float*)d_in[2];
    const float* Wv  = (const float*)d_in[3];
    const float* Wo  = (const float*)d_in[4];
    float* out = (float*)d_out;

    float *Qb, *Kb, *Vb;
    cudaGetSymbolAddress((void**)&Qb, g_Q);
    cudaGetSymbolAddress((void**)&Kb, g_K);
    cudaGetSymbolAddress((void**)&Vb, g_V);

    __nv_bfloat16 *Hh, *Hl, *WqtH, *WqtL, *WktH, *WktL, *WvtH, *WvtL, *WotH, *WotL;
    __nv_bfloat16 *Ch, *Cl, *Qh, *Ql, *Kh, *Kl, *VtH, *VtL;
    cudaGetSymbolAddress((void**)&Hh,   g_Hh);
    cudaGetSymbolAddress((void**)&Hl,   g_Hl);
    cudaGetSymbolAddress((void**)&WqtH, g_WqtH);
    cudaGetSymbolAddress((void**)&WqtL, g_WqtL);
    cudaGetSymbolAddress((void**)&WktH, g_WktH);
    cudaGetSymbolAddress((void**)&WktL, g_WktL);
    cudaGetSymbolAddress((void**)&WvtH, g_WvtH);
    cudaGetSymbolAddress((void**)&WvtL, g_WvtL);
    cudaGetSymbolAddress((void**)&WotH, g_WotH);
    cudaGetSymbolAddress((void**)&WotL, g_WotL);
    cudaGetSymbolAddress((void**)&Ch,   g_Ch);
    cudaGetSymbolAddress((void**)&Cl,   g_Cl);
    cudaGetSymbolAddress((void**)&Qh,   g_Qh);
    cudaGetSymbolAddress((void**)&Ql,   g_Ql);
    cudaGetSymbolAddress((void**)&Kh,   g_Kh);
    cudaGetSymbolAddress((void**)&Kl,   g_Kl);
    cudaGetSymbolAddress((void**)&VtH,  g_VtH);
    cudaGetSymbolAddress((void**)&VtL,  g_VtL);

    cudaFuncSetAttribute(gemm_mma_kernel, cudaFuncAttributeMaxDynamicSharedMemorySize,
                         GEMM_SMEM);
    cudaFuncSetAttribute(attn_tc_kernel, cudaFuncAttributeMaxDynamicSharedMemorySize,
                         ATTN_SMEM);

    rope_tables_kernel<<<(SEQ * 128 + 255) / 256, 256>>>();

    // splits / transposes of inputs
    split_kernel<<<(MROWS * EMBED / 4 + 255) / 256, 256>>>(hid, Hh, Hl, MROWS * EMBED / 4);
    tsplit_kernel<<<dim3(QCOLS / 32, EMBED / 32), dim3(32, 8)>>>(Wq, WqtH, WqtL, EMBED, QCOLS);
    tsplit_kernel<<<dim3(KCOLS / 32, EMBED / 32), dim3(32, 8)>>>(Wk, WktH, WktL, EMBED, KCOLS);
    tsplit_kernel<<<dim3(KCOLS / 32, EMBED / 32), dim3(32, 8)>>>(Wv, WvtH, WvtL, EMBED, KCOLS);
    tsplit_kernel<<<dim3(EMBED / 32, QCOLS / 32), dim3(32, 8)>>>(Wo, WotH, WotL, QCOLS, EMBED);

    // projections (mma.sync bf16x3)
    gemm_mma_kernel<<<dim3(QCOLS / 128, MROWS / 128), 256, GEMM_SMEM>>>(
        Hh, Hl, WqtH, WqtL, Qb, MROWS, QCOLS, EMBED);
    gemm_mma_kernel<<<dim3(KCOLS / 128, MROWS / 128), 256, GEMM_SMEM>>>(
        Hh, Hl, WktH, WktL, Kb, MROWS, KCOLS, EMBED);
    gemm_mma_kernel<<<dim3(KCOLS / 128, MROWS / 128), 256, GEMM_SMEM>>>(
        Hh, Hl, WvtH, WvtL, Vb, MROWS, KCOLS, EMBED);

    // RoPE + split to bf16 attention operands; V transpose+split
    rope_split_kernel<<<(MROWS * NH  * 128 + 255) / 256, 256>>>(Qb, Qh, Ql, NH);
    rope_split_kernel<<<(MROWS * NKV * 128 + 255) / 256, 256>>>(Kb, Kh, Kl, NKV);
    vtsplit_kernel<<<dim3(SEQ / 32, KCOLS / 32, BATCH), dim3(32, 8)>>>(Vb, VtH, VtL);

    // tensor-core attention -> Ch/Cl bf16 splits
    attn_tc_kernel<<<dim3(SEQ / 64, BATCH * NH), 256, ATTN_SMEM>>>(
        Qh, Ql, Kh, Kl, VtH, VtL, Ch, Cl);

    // output projection straight into d_out
    gemm_mma_kernel<<<dim3(EMBED / 128, MROWS / 128), 256, GEMM_SMEM>>>(
        Ch, Cl, WotH, WotL, out, MROWS, EMBED, QCOLS);
}

// round 11
// speedup vs baseline: 2.4796x; 1.0311x over previous
#include <cuda_runtime.h>
#include <cuda_bf16.h>
#include <math.h>
#include <stdint.h>

// ---------------------------------------------------------------------------
// Problem constants
// ---------------------------------------------------------------------------
#define BATCH   2
#define SEQ     2048
#define EMBED   3584
#define NH      16
#define NKV     8
#define HDIM    256
#define MROWS   (BATCH*SEQ)          // 4096
#define QCOLS   (NH*HDIM)            // 4096
#define KCOLS   (NKV*HDIM)           // 2048
#define NPACK   (QCOLS + 2*KCOLS)    // 8192 packed QKV columns
#define WINDOW  1024

// ---------------------------------------------------------------------------
// Static device scratch (no cudaMalloc allowed)
// ---------------------------------------------------------------------------
__device__ float g_V  [(size_t)MROWS*KCOLS];
__device__ float g_cos[SEQ*(HDIM/2)];
__device__ float g_sin[SEQ*(HDIM/2)];

// bf16 hi/lo splits
__device__ __nv_bfloat16 g_Hh [(size_t)MROWS*EMBED];
__device__ __nv_bfloat16 g_Hl [(size_t)MROWS*EMBED];
__device__ __nv_bfloat16 g_WpH[(size_t)NPACK*EMBED];   // packed Wq|Wk|Wv, transposed+split
__device__ __nv_bfloat16 g_WpL[(size_t)NPACK*EMBED];
__device__ __nv_bfloat16 g_WotH[(size_t)EMBED*QCOLS];
__device__ __nv_bfloat16 g_WotL[(size_t)EMBED*QCOLS];
__device__ __nv_bfloat16 g_Ch  [(size_t)MROWS*QCOLS];
__device__ __nv_bfloat16 g_Cl  [(size_t)MROWS*QCOLS];

// attention operands (bf16 splits)
__device__ __nv_bfloat16 g_Qh [(size_t)MROWS*QCOLS];
__device__ __nv_bfloat16 g_Ql [(size_t)MROWS*QCOLS];
__device__ __nv_bfloat16 g_Kh [(size_t)MROWS*KCOLS];
__device__ __nv_bfloat16 g_Kl [(size_t)MROWS*KCOLS];
__device__ __nv_bfloat16 g_VtH[(size_t)MROWS*KCOLS];   // per-batch transposed [KCOLS][SEQ]
__device__ __nv_bfloat16 g_VtL[(size_t)MROWS*KCOLS];

// ---------------------------------------------------------------------------
// PTX helpers (sm_100-safe: no tcgen05, no clusters)
// ---------------------------------------------------------------------------
__device__ __forceinline__ uint32_t smem_u32(const void* p) {
    uint32_t a;
    asm("{ .reg .u64 t; cvta.to.shared.u64 t, %1; cvt.u32.u64 %0, t; }" : "=r"(a) : "l"(p));
    return a;
}
__device__ __forceinline__ void cp16(uint32_t dst, const void* src) {
    asm volatile("cp.async.cg.shared.global [%0], [%1], 16;" :: "r"(dst), "l"(src) : "memory");
}
__device__ __forceinline__ void ldmx4(uint32_t* r, uint32_t addr) {
    asm volatile("ldmatrix.sync.aligned.m8n8.x4.shared.b16 {%0,%1,%2,%3}, [%4];"
                 : "=r"(r[0]), "=r"(r[1]), "=r"(r[2]), "=r"(r[3]) : "r"(addr));
}
__device__ __forceinline__ void mma_bf16(float* c, const uint32_t* a,
                                         uint32_t b0, uint32_t b1) {
    asm volatile(
        "mma.sync.aligned.m16n8k16.row.col.f32.bf16.bf16.f32 "
        "{%0,%1,%2,%3}, {%4,%5,%6,%7}, {%8,%9}, {%0,%1,%2,%3};"
        : "+f"(c[0]), "+f"(c[1]), "+f"(c[2]), "+f"(c[3])
        : "r"(a[0]), "r"(a[1]), "r"(a[2]), "r"(a[3]), "r"(b0), "r"(b1));
}

// FMA-pipe exp (no MUFU): e^x for |x| <= ~85, rel err ~1.5e-7
__device__ __forceinline__ float fexp(float x) {
    float y  = x * 1.4426950408889634f;          // log2(e)
    float fm = y + 12582912.0f;                  // round-to-nearest via magic
    float nf = fm - 12582912.0f;
    float f  = y - nf;                           // [-0.5, 0.5]
    int   sc = ((__float_as_int(fm) - 0x4B400000) + 127) << 23;
    float t  = f * 0.6931471805599453f;
    float p  = 1.0f + t*(1.0f + t*(0.5f + t*(0.16666667f +
               t*(0.041666667f + t*(0.008333334f + t*0.0013888889f)))));
    return p * __int_as_float(sc);
}
// FMA-pipe reciprocal (bit-hack + 3 Newton)
__device__ __forceinline__ float frcp(float d) {
    float r = __int_as_float(0x7EF311C3 - __float_as_int(d));
    r = r * (2.0f - d * r);
    r = r * (2.0f - d * r);
    r = r * (2.0f - d * r);
    return r;
}

// ---------------------------------------------------------------------------
// fp32 -> bf16 hi/lo split (vectorized)
// ---------------------------------------------------------------------------
__global__ void split_kernel(const float* __restrict__ in,
                             __nv_bfloat16* __restrict__ hi,
                             __nv_bfloat16* __restrict__ lo, int n4)
{
    int i = blockIdx.x * 256 + threadIdx.x;
    if (i >= n4) return;
    float4 v = ((const float4*)in)[i];
    __nv_bfloat16 h0 = __float2bfloat16(v.x);
    __nv_bfloat16 h1 = __float2bfloat16(v.y);
    __nv_bfloat16 h2 = __float2bfloat16(v.z);
    __nv_bfloat16 h3 = __float2bfloat16(v.w);
    __nv_bfloat16 l0 = __float2bfloat16(v.x - __bfloat162float(h0));
    __nv_bfloat16 l1 = __float2bfloat16(v.y - __bfloat162float(h1));
    __nv_bfloat16 l2 = __float2bfloat16(v.z - __bfloat162float(h2));
    __nv_bfloat16 l3 = __float2bfloat16(v.w - __bfloat162float(h3));
    ((__nv_bfloat162*)hi)[2*i]   = __halves2bfloat162(h0, h1);
    ((__nv_bfloat162*)hi)[2*i+1] = __halves2bfloat162(h2, h3);
    ((__nv_bfloat162*)lo)[2*i]   = __halves2bfloat162(l0, l1);
    ((__nv_bfloat162*)lo)[2*i+1] = __halves2bfloat162(l2, l3);
}

// ---------------------------------------------------------------------------
// Transpose + split: W [K,N] fp32 -> Th/Tl rows [rowoff + perm(n)][K] bf16.
// perm=1 interleaves RoPE pairs: col i<128 -> 2i, col i>=128 -> 2(i-128)+1
// (within each 256-wide head block) so GEMM output pairs are adjacent.
// ---------------------------------------------------------------------------
__global__ void tsplit_kernel(const float* __restrict__ W,
                              __nv_bfloat16* __restrict__ Th,
                              __nv_bfloat16* __restrict__ Tl, int K, int N,
                              int perm, int rowoff)
{
    __shared__ float t[32][33];
    int n0 = blockIdx.x * 32, k0 = blockIdx.y * 32;
    int tx = threadIdx.x, ty = threadIdx.y;
#pragma unroll
    for (int i = 0; i < 32; i += 8)
        t[ty + i][tx] = W[(size_t)(k0 + ty + i) * N + n0 + tx];
    __syncthreads();
#pragma unroll
    for (int i = 0; i < 32; i += 8) {
        float v = t[tx][ty + i];
        __nv_bfloat16 h = __float2bfloat16(v);
        __nv_bfloat16 l = __float2bfloat16(v - __bfloat162float(h));
        int n = n0 + ty + i;
        int nb = n & 255;
        int np = perm ? ((n & ~255) + ((nb < 128) ? (nb << 1) : (((nb - 128) << 1) | 1)))
                      : n;
        size_t o = (size_t)(rowoff + np) * K + k0 + tx;
        Th[o] = h;
        Tl[o] = l;
    }
}

// ---------------------------------------------------------------------------
// V transpose+split per batch: g_V [b*SEQ+s][KCOLS] -> Vt [b][KCOLS][SEQ]
// ---------------------------------------------------------------------------
__global__ void vtsplit_kernel(const float* __restrict__ V,
                               __nv_bfloat16* __restrict__ Th,
                               __nv_bfloat16* __restrict__ Tl)
{
    __shared__ float t[32][33];
    int s0 = blockIdx.x * 32, c0 = blockIdx.y * 32, b = blockIdx.z;
    int tx = threadIdx.x, ty = threadIdx.y;
#pragma unroll
    for (int i = 0; i < 32; i += 8)
        t[ty + i][tx] = V[((size_t)b * SEQ + s0 + ty + i) * KCOLS + c0 + tx];
    __syncthreads();
#pragma unroll
    for (int i = 0; i < 32; i += 8) {
        float v = t[tx][ty + i];
        __nv_bfloat16 h = __float2bfloat16(v);
        __nv_bfloat16 l = __float2bfloat16(v - __bfloat162float(h));
        size_t o = ((size_t)b * KCOLS + c0 + ty + i) * SEQ + s0 + tx;
        Th[o] = h;
        Tl[o] = l;
    }
}

// ---------------------------------------------------------------------------
// RoPE tables (double precision)
// ---------------------------------------------------------------------------
__global__ void rope_tables_kernel()
{
    int idx = blockIdx.x * 256 + threadIdx.x;
    if (idx >= SEQ * (HDIM / 2)) return;
    int i = idx & 127;
    int pos = idx >> 7;
    double invf = pow(10000.0, -(double)(2 * i) / (double)HDIM);
    double ang = (double)pos * invf;
    g_cos[idx] = (float)cos(ang);
    g_sin[idx] = (float)sin(ang);
}

// ---------------------------------------------------------------------------
// mma.sync bf16x3 GEMM: 2-stage pipeline, 2 CTAs/SM, term-ordered MMAs.
// mode 0: C[M,N] fp32 plain.
// mode 1: fused QKV (N=8192 packed, perm'd Q/K cols): epilogue applies RoPE
//         and writes Qh/Ql/Kh/Kl bf16 splits directly; V segment -> Vb fp32.
// ---------------------------------------------------------------------------
#define GKC       32
#define GSTRIDE   40
#define GTILE_B   (128*GSTRIDE*2)    // 10240 B per tile
#define GSTAGE_B  (4*GTILE_B)        // Ah, Al, Bh, Bl = 40960 B
#define GEMM_SMEM (2*GSTAGE_B)       // 81920 B -> 2 CTAs/SM

__device__ __forceinline__ void fill_stage(uint32_t stb,
                                           const __nv_bfloat16* Ah0,
                                           const __nv_bfloat16* Al0,
                                           const __nv_bfloat16* Bh0,
                                           const __nv_bfloat16* Bl0,
                                           int K, int tid)
{
    const __nv_bfloat16* srcs[4] = {Ah0, Al0, Bh0, Bl0};
#pragma unroll
    for (int t = 0; t < 4; t++) {
        uint32_t tb = stb + t * GTILE_B;
        const char* s = (const char*)srcs[t];
#pragma unroll
        for (int i = 0; i < 2; i++) {
            int id = tid + i * 256;
            int row = id >> 2, ch = id & 3;
            cp16(tb + row * (GSTRIDE * 2) + ch * 16,
                 s + (size_t)row * K * 2 + ch * 16);
        }
    }
    asm volatile("cp.async.commit_group;" ::: "memory");
}

__global__ void __launch_bounds__(256, 2)
gemm_mma_kernel(const __nv_bfloat16* __restrict__ Ah,
                const __nv_bfloat16* __restrict__ Al,
                const __nv_bfloat16* __restrict__ Bh,
                const __nv_bfloat16* __restrict__ Bl,
                float* __restrict__ C, int M, int N, int K,
                int fused,
                __nv_bfloat16* __restrict__ Qh, __nv_bfloat16* __restrict__ Ql,
                __nv_bfloat16* __restrict__ Kh, __nv_bfloat16* __restrict__ Kl,
                float* __restrict__ Vb)
{
    extern __shared__ char gsm[];
    const uint32_t sbase = smem_u32(gsm);
    const int tid = threadIdx.x;
    const int wid = tid >> 5, lane = tid & 31;
    const int wm = wid & 1, wn = wid >> 1;
    const int m0 = blockIdx.y * 128, n0 = blockIdx.x * 128;

    uint32_t a_off[4], b_off[2];
#pragma unroll
    for (int mt = 0; mt < 4; mt++)
        a_off[mt] = ((wm * 64 + mt * 16 + (lane & 15)) * GSTRIDE
                     + (lane >> 4) * 8) * 2;
#pragma unroll
    for (int np = 0; np < 2; np++)
        b_off[np] = ((wn * 32 + np * 16 + (lane & 7) + ((lane >> 4) & 1) * 8) * GSTRIDE
                     + ((lane >> 3) & 1) * 8) * 2;

    const __nv_bfloat16* Ah0 = Ah + (size_t)m0 * K;
    const __nv_bfloat16* Al0 = Al + (size_t)m0 * K;
    const __nv_bfloat16* Bh0 = Bh + (size_t)n0 * K;
    const __nv_bfloat16* Bl0 = Bl + (size_t)n0 * K;

    float acc[4][4][4];
#pragma unroll
    for (int mt = 0; mt < 4; mt++)
#pragma unroll
        for (int nt = 0; nt < 4; nt++)
#pragma unroll
            for (int r = 0; r < 4; r++) acc[mt][nt][r] = 0.f;

    const int NC = K / GKC;

    // prologue: 2 stages in flight
#pragma unroll
    for (int c = 0; c < 2; c++)
        fill_stage(sbase + c * GSTAGE_B, Ah0 + c * GKC, Al0 + c * GKC,
                   Bh0 + c * GKC, Bl0 + c * GKC, K, tid);

    for (int c = 0; c < NC; c++) {
        const uint32_t stb = sbase + (c & 1) * GSTAGE_B;
        asm volatile("cp.async.wait_group %0;" :: "n"(1) : "memory");
        __syncthreads();

#pragma unroll
        for (int ks = 0; ks < 2; ks++) {
            const uint32_t ko = ks * 32;
            uint32_t ax[4][4], bx[2][4];

            // ---- term 1: Ah * Bh ----
#pragma unroll
            for (int mt = 0; mt < 4; mt++) ldmx4(ax[mt], stb + 0 * GTILE_B + a_off[mt] + ko);
#pragma unroll
            for (int np = 0; np < 2; np++) ldmx4(bx[np], stb + 2 * GTILE_B + b_off[np] + ko);
#pragma unroll
            for (int mt = 0; mt < 4; mt++)
#pragma unroll
                for (int nt = 0; nt < 4; nt++) {
                    const int np = nt >> 1, bi = (nt & 1) * 2;
                    mma_bf16(acc[mt][nt], ax[mt], bx[np][bi], bx[np][bi + 1]);
                }

            // ---- term 2: Al * Bh (reuse Bh frags) ----
#pragma unroll
            for (int mt = 0; mt < 4; mt++) ldmx4(ax[mt], stb + 1 * GTILE_B + a_off[mt] + ko);
#pragma unroll
            for (int mt = 0; mt < 4; mt++)
#pragma unroll
                for (int nt = 0; nt < 4; nt++) {
                    const int np = nt >> 1, bi = (nt & 1) * 2;
                    mma_bf16(acc[mt][nt], ax[mt], bx[np][bi], bx[np][bi + 1]);
                }

            // ---- term 3: Ah * Bl (reload Ah, load Bl) ----
#pragma unroll
            for (int mt = 0; mt < 4; mt++) ldmx4(ax[mt], stb + 0 * GTILE_B + a_off[mt] + ko);
#pragma unroll
            for (int np = 0; np < 2; np++) ldmx4(bx[np], stb + 3 * GTILE_B + b_off[np] + ko);
#pragma unroll
            for (int mt = 0; mt < 4; mt++)
#pragma unroll
                for (int nt = 0; nt < 4; nt++) {
                    const int np = nt >> 1, bi = (nt & 1) * 2;
                    mma_bf16(acc[mt][nt], ax[mt], bx[np][bi], bx[np][bi + 1]);
                }
        }

        __syncthreads();
        const int cn = c + 2;
        if (cn < NC)
            fill_stage(stb, Ah0 + cn * GKC, Al0 + cn * GKC,
                       Bh0 + cn * GKC, Bl0 + cn * GKC, K, tid);
    }

    const int rr = lane >> 2, cc = (lane & 3) * 2;

    if (!fused) {
        // plain fp32 epilogue
#pragma unroll
        for (int mt = 0; mt < 4; mt++) {
            const size_t mA = (size_t)(m0 + wm * 64 + mt * 16 + rr);
#pragma unroll
            for (int nt = 0; nt < 4; nt++) {
                const int n = n0 + wn * 32 + nt * 8 + cc;
                *(float2*)(C + mA * N + n) =
                    make_float2(acc[mt][nt][0], acc[mt][nt][1]);
                *(float2*)(C + (mA + 8) * N + n) =
                    make_float2(acc[mt][nt][2], acc[mt][nt][3]);
            }
        }
        return;
    }

    // fused QKV epilogue: segment by packed column
    if (n0 >= QCOLS + KCOLS) {
        // V segment: plain fp32 into Vb (stride KCOLS)
#pragma unroll
        for (int mt = 0; mt < 4; mt++) {
            const size_t mA = (size_t)(m0 + wm * 64 + mt * 16 + rr);
#pragma unroll
            for (int nt = 0; nt < 4; nt++) {
                const int n = (n0 - (QCOLS + KCOLS)) + wn * 32 + nt * 8 + cc;
                *(float2*)(Vb + mA * KCOLS + n) =
                    make_float2(acc[mt][nt][0], acc[mt][nt][1]);
                *(float2*)(Vb + (mA + 8) * KCOLS + n) =
                    make_float2(acc[mt][nt][2], acc[mt][nt][3]);
            }
        }
        return;
    }

    // Q or K segment: RoPE + bf16 split, write un-permuted layout
    __nv_bfloat16 *Xh, *Xl;
    int xs, segbase;
    if (n0 < QCOLS) { Xh = Qh; Xl = Ql; xs = QCOLS; segbase = 0; }
    else            { Xh = Kh; Xl = Kl; xs = KCOLS; segbase = QCOLS; }

#pragma unroll
    for (int mt = 0; mt < 4; mt++) {
        const int mA = m0 + wm * 64 + mt * 16 + rr;
#pragma unroll
        for (int nt = 0; nt < 4; nt++) {
            const int colp = (n0 - segbase) + wn * 32 + nt * 8 + cc; // even
            const int head = colp >> 8;
            const int i    = (colp & 255) >> 1;        // 0..127
            const int ca   = head * 256 + i;
            const int cb   = ca + 128;
#pragma unroll
            for (int rh = 0; rh < 2; rh++) {
                const int m   = mA + rh * 8;
                const int pos = m & (SEQ - 1);
                const float co = g_cos[pos * 128 + i];
                const float si = g_sin[pos * 128 + i];
                const float x1 = acc[mt][nt][rh * 2 + 0];
                const float x2 = acc[mt][nt][rh * 2 + 1];
                const float y1 = x1 * co - x2 * si;
                const float y2 = x2 * co + x1 * si;
                const __nv_bfloat16 h1 = __float2bfloat16(y1);
                const __nv_bfloat16 h2 = __float2bfloat16(y2);
                const size_t rb = (size_t)m * xs;
                Xh[rb + ca] = h1;
                Xh[rb + cb] = h2;
                Xl[rb + ca] = __float2bfloat16(y1 - __bfloat162float(h1));
                Xl[rb + cb] = __float2bfloat16(y2 - __bfloat162float(h2));
            }
        }
    }
}

// ---------------------------------------------------------------------------
// Tensor-core flash attention, bf16x3, no-max softmax (|logit| <= 50),
// FMA-pipe exp/rcp (zero MUFU in the hot path). Unchanged from passing R9.
// ---------------------------------------------------------------------------
#define DST 264   // Q/K smem row stride (bf16)
#define VST 72    // Vt smem row stride (bf16)
#define PST 72    // P smem row stride (bf16)
#define oQh 0
#define oQl 33792
#define oKh 67584
#define oKl 101376
#define oVh 135168
#define oVl 172032
#define oPh 208896
#define oPl 218112
#define oLrow 227328
#define ATTN_SMEM (227328 + 256)

__global__ void __launch_bounds__(256, 1)
attn_tc_kernel(const __nv_bfloat16* __restrict__ Qh, const __nv_bfloat16* __restrict__ Ql,
               const __nv_bfloat16* __restrict__ Kh, const __nv_bfloat16* __restrict__ Kl,
               const __nv_bfloat16* __restrict__ Vth, const __nv_bfloat16* __restrict__ Vtl,
               __nv_bfloat16* __restrict__ Ch, __nv_bfloat16* __restrict__ Cl)
{
    extern __shared__ char smraw[];
    const uint32_t sb = smem_u32(smraw);
    float* lrow = (float*)(smraw + oLrow);

    const int tid = threadIdx.x;
    const int wid = tid >> 5, lane = tid & 31;
    const int wq = wid & 3, wh = wid >> 2;
    const int b  = blockIdx.y >> 4;
    const int h  = blockIdx.y & 15;
    const int kvh = h >> 1;
    const int q0 = blockIdx.x * 64;

    const char* gQh = (const char*)(Qh + ((size_t)(b * SEQ + q0)) * QCOLS + h * HDIM);
    const char* gQl = (const char*)(Ql + ((size_t)(b * SEQ + q0)) * QCOLS + h * HDIM);
    const char* gKh = (const char*)(Kh + ((size_t)(b * SEQ)) * KCOLS + kvh * HDIM);
    const char* gKl = (const char*)(Kl + ((size_t)(b * SEQ)) * KCOLS + kvh * HDIM);
    const char* gVh = (const char*)(Vth + ((size_t)(b * KCOLS + kvh * HDIM)) * SEQ);
    const char* gVl = (const char*)(Vtl + ((size_t)(b * KCOLS + kvh * HDIM)) * SEQ);

    if (tid < 64) lrow[tid] = 0.f;

    int klo = q0 - WINDOW;       if (klo < 0) klo = 0;
    int khi = q0 + 64 + WINDOW;  if (khi > SEQ) khi = SEQ;
    const int kt0 = klo >> 6;
    const int ntiles = (khi >> 6) - kt0;

#pragma unroll
    for (int i = 0; i < 8; i++) {
        int id = tid + i * 256;
        int row = id >> 5, ch = id & 31;
        cp16(sb + oQh + row * (DST * 2) + ch * 16, gQh + (size_t)row * (QCOLS * 2) + ch * 16);
        cp16(sb + oQl + row * (DST * 2) + ch * 16, gQl + (size_t)row * (QCOLS * 2) + ch * 16);
    }
    {
        int kb = kt0 * 64;
#pragma unroll
        for (int i = 0; i < 8; i++) {
            int id = tid + i * 256;
            int row = id >> 5, ch = id & 31;
            cp16(sb + oKh + row * (DST * 2) + ch * 16, gKh + (size_t)(kb + row) * (KCOLS * 2) + ch * 16);
            cp16(sb + oKl + row * (DST * 2) + ch * 16, gKl + (size_t)(kb + row) * (KCOLS * 2) + ch * 16);
        }
        asm volatile("cp.async.commit_group;" ::: "memory");
#pragma unroll
        for (int i = 0; i < 8; i++) {
            int id = tid + i * 256;
            int row = id >> 3, ch = id & 7;
            cp16(sb + oVh + row * (VST * 2) + ch * 16, gVh + (size_t)row * (SEQ * 2) + kb * 2 + ch * 16);
            cp16(sb + oVl + row * (VST * 2) + ch * 16, gVl + (size_t)row * (SEQ * 2) + kb * 2 + ch * 16);
        }
        asm volatile("cp.async.commit_group;" ::: "memory");
    }
    asm volatile("cp.async.wait_group %0;" :: "n"(1) : "memory");
    __syncthreads();

    const uint32_t a_off = ((wq * 16 + (lane & 15)) * DST + (lane >> 4) * 8) * 2;
    uint32_t bs_off[2];
#pragma unroll
    for (int np = 0; np < 2; np++)
        bs_off[np] = ((wh * 32 + np * 16 + (lane & 7) + ((lane >> 4) & 1) * 8) * DST
                      + ((lane >> 3) & 1) * 8) * 2;
    const uint32_t ap_off = ((wq * 16 + (lane & 15)) * PST + (lane >> 4) * 8) * 2;
    uint32_t bv_off[8];
#pragma unroll
    for (int np = 0; np < 8; np++)
        bv_off[np] = ((wh * 128 + np * 16 + (lane & 7) + ((lane >> 4) & 1) * 8) * VST
                      + ((lane >> 3) & 1) * 8) * 2;

    float oacc[16][4];
#pragma unroll
    for (int nt = 0; nt < 16; nt++)
#pragma unroll
        for (int r = 0; r < 4; r++) oacc[nt][r] = 0.f;

    const int r0 = wq * 16 + (lane >> 2), r1 = r0 + 8;
    const int qg0 = q0 + r0, qg1 = q0 + r1;

    for (int t = 0; t < ntiles; t++) {
        const int kbase = (kt0 + t) * 64;

        float sacc[4][4];
#pragma unroll
        for (int nt = 0; nt < 4; nt++)
#pragma unroll
            for (int r = 0; r < 4; r++) sacc[nt][r] = 0.f;

#pragma unroll 4
        for (int ks = 0; ks < 16; ks++) {
            const uint32_t ko = ks * 32;
            uint32_t qhf[4], qlf[4], khf[2][4], klf[2][4];
            ldmx4(qhf, sb + oQh + a_off + ko);
            ldmx4(qlf, sb + oQl + a_off + ko);
#pragma unroll
            for (int np = 0; np < 2; np++) {
                ldmx4(khf[np], sb + oKh + bs_off[np] + ko);
                ldmx4(klf[np], sb + oKl + bs_off[np] + ko);
            }
#pragma unroll
            for (int nt = 0; nt < 4; nt++) {
                const int np = nt >> 1, bi = (nt & 1) * 2;
                mma_bf16(sacc[nt], qhf, khf[np][bi], khf[np][bi + 1]);
                mma_bf16(sacc[nt], qlf, khf[np][bi], khf[np][bi + 1]);
                mma_bf16(sacc[nt], qhf, klf[np][bi], klf[np][bi + 1]);
            }
        }

        float psum0 = 0.f, psum1 = 0.f;
#pragma unroll
        for (int nt = 0; nt < 4; nt++) {
            const int cl = wh * 32 + nt * 8 + (lane & 3) * 2;
            const int cg = kbase + cl;
            float p[4];
#pragma unroll
            for (int e = 0; e < 4; e++) {
                const int qg = (e < 2) ? qg0 : qg1;
                const int kg = cg + (e & 1);
                int dlt = qg - kg; if (dlt < 0) dlt = -dlt;
                if (dlt <= WINDOW) {
                    float E = fexp(sacc[nt][e] * 0.0025f);
                    float l = fmaf(-100.f, frcp(E + 1.f), 50.f);
                    p[e] = fexp(l);
                } else p[e] = 0.f;
            }
            psum0 += p[0] + p[1];
            psum1 += p[2] + p[3];
            __nv_bfloat16 h0 = __float2bfloat16(p[0]), h1 = __float2bfloat16(p[1]);
            __nv_bfloat16 h2 = __float2bfloat16(p[2]), h3 = __float2bfloat16(p[3]);
            *(__nv_bfloat162*)(smraw + oPh + (r0 * PST + cl) * 2) = __halves2bfloat162(h0, h1);
            *(__nv_bfloat162*)(smraw + oPh + (r1 * PST + cl) * 2) = __halves2bfloat162(h2, h3);
            *(__nv_bfloat162*)(smraw + oPl + (r0 * PST + cl) * 2) =
                __halves2bfloat162(__float2bfloat16(p[0] - __bfloat162float(h0)),
                                   __float2bfloat16(p[1] - __bfloat162float(h1)));
            *(__nv_bfloat162*)(smraw + oPl + (r1 * PST + cl) * 2) =
                __halves2bfloat162(__float2bfloat16(p[2] - __bfloat162float(h2)),
                                   __float2bfloat16(p[3] - __bfloat162float(h3)));
        }
        psum0 += __shfl_xor_sync(0xffffffffu, psum0, 1);
        psum0 += __shfl_xor_sync(0xffffffffu, psum0, 2);
        psum1 += __shfl_xor_sync(0xffffffffu, psum1, 1);
        psum1 += __shfl_xor_sync(0xffffffffu, psum1, 2);
        if ((lane & 3) == 0) {
            atomicAdd(&lrow[r0], psum0);
            atomicAdd(&lrow[r1], psum1);
        }

        asm volatile("cp.async.wait_group %0;" :: "n"(0) : "memory");
        __syncthreads();

        if (t + 1 < ntiles) {
            int kb = kbase + 64;
#pragma unroll
            for (int i = 0; i < 8; i++) {
                int id = tid + i * 256;
                int row = id >> 5, ch = id & 31;
                cp16(sb + oKh + row * (DST * 2) + ch * 16, gKh + (size_t)(kb + row) * (KCOLS * 2) + ch * 16);
                cp16(sb + oKl + row * (DST * 2) + ch * 16, gKl + (size_t)(kb + row) * (KCOLS * 2) + ch * 16);
            }
            asm volatile("cp.async.commit_group;" ::: "memory");
        }

#pragma unroll
        for (int kp = 0; kp < 4; kp++) {
            const uint32_t ko = kp * 32;
            uint32_t pah[4], pal[4];
            ldmx4(pah, sb + oPh + ap_off + ko);
            ldmx4(pal, sb + oPl + ap_off + ko);
#pragma unroll
            for (int np = 0; np < 8; np++) {
                uint32_t vbh[4], vbl[4];
                ldmx4(vbh, sb + oVh + bv_off[np] + ko);
                ldmx4(vbl, sb + oVl + bv_off[np] + ko);
#pragma unroll
                for (int i = 0; i < 2; i++) {
                    const int nt = np * 2 + i, bi = i * 2;
                    mma_bf16(oacc[nt], pah, vbh[bi], vbh[bi + 1]);
                    mma_bf16(oacc[nt], pal, vbh[bi], vbh[bi + 1]);
                    mma_bf16(oacc[nt], pah, vbl[bi], vbl[bi + 1]);
                }
            }
        }
        __syncthreads();

        if (t + 1 < ntiles) {
            int kb = kbase + 64;
#pragma unroll
            for (int i = 0; i < 8; i++) {
                int id = tid + i * 256;
                int row = id >> 3, ch = id & 7;
                cp16(sb + oVh + row * (VST * 2) + ch * 16, gVh + (size_t)row * (SEQ * 2) + kb * 2 + ch * 16);
                cp16(sb + oVl + row * (VST * 2) + ch * 16, gVl + (size_t)row * (SEQ * 2) + kb * 2 + ch * 16);
            }
            asm volatile("cp.async.commit_group;" ::: "memory");
            asm volatile("cp.async.wait_group %0;" :: "n"(1) : "memory");
        }
        __syncthreads();
    }

    const float inv0 = 1.0f / lrow[r0];
    const float inv1 = 1.0f / lrow[r1];
    const size_t row0 = (size_t)(b * SEQ + q0 + r0) * QCOLS;
    const size_t row1 = (size_t)(b * SEQ + q0 + r1) * QCOLS;
#pragma unroll
    for (int nt = 0; nt < 16; nt++) {
        const int col = h * HDIM + wh * 128 + nt * 8 + (lane & 3) * 2;
        float v0 = oacc[nt][0] * inv0, v1 = oacc[nt][1] * inv0;
        float v2 = oacc[nt][2] * inv1, v3 = oacc[nt][3] * inv1;
        __nv_bfloat16 h0 = __float2bfloat16(v0), h1 = __float2bfloat16(v1);
        __nv_bfloat16 h2 = __float2bfloat16(v2), h3 = __float2bfloat16(v3);
        *(__nv_bfloat162*)(Ch + row0 + col) = __halves2bfloat162(h0, h1);
        *(__nv_bfloat162*)(Ch + row1 + col) = __halves2bfloat162(h2, h3);
        *(__nv_bfloat162*)(Cl + row0 + col) =
            __halves2bfloat162(__float2bfloat16(v0 - __bfloat162float(h0)),
                               __float2bfloat16(v1 - __bfloat162float(h1)));
        *(__nv_bfloat162*)(Cl + row1 + col) =
            __halves2bfloat162(__float2bfloat16(v2 - __bfloat162float(h2)),
                               __float2bfloat16(v3 - __bfloat162float(h3)));
    }
}

// ---------------------------------------------------------------------------
// launch
// ---------------------------------------------------------------------------
extern "C" void kernel_launch(void* const* d_in, const int* in_sizes, int n_in,
                              void* d_out, int out_size)
{
    const float* hid = (const float*)d_in[0];
    const float* Wq  = (const float*)d_in[1];
    const float* Wk  = (const float*)d_in[2];
    const float* Wv  = (const float*)d_in[3];
    const float* Wo  = (const float*)d_in[4];
    float* out = (float*)d_out;

    float *Vb;
    cudaGetSymbolAddress((void**)&Vb, g_V);

    __nv_bfloat16 *Hh, *Hl, *WpH, *WpL, *WotH, *WotL;
    __nv_bfloat16 *Ch, *Cl, *Qh, *Ql, *Kh, *Kl, *VtH, *VtL;
    cudaGetSymbolAddress((void**)&Hh,   g_Hh);
    cudaGetSymbolAddress((void**)&Hl,   g_Hl);
    cudaGetSymbolAddress((void**)&WpH,  g_WpH);
    cudaGetSymbolAddress((void**)&WpL,  g_WpL);
    cudaGetSymbolAddress((void**)&WotH, g_WotH);
    cudaGetSymbolAddress((void**)&WotL, g_WotL);
    cudaGetSymbolAddress((void**)&Ch,   g_Ch);
    cudaGetSymbolAddress((void**)&Cl,   g_Cl);
    cudaGetSymbolAddress((void**)&Qh,   g_Qh);
    cudaGetSymbolAddress((void**)&Ql,   g_Ql);
    cudaGetSymbolAddress((void**)&Kh,   g_Kh);
    cudaGetSymbolAddress((void**)&Kl,   g_Kl);
    cudaGetSymbolAddress((void**)&VtH,  g_VtH);
    cudaGetSymbolAddress((void**)&VtL,  g_VtL);

    cudaFuncSetAttribute(gemm_mma_kernel, cudaFuncAttributeMaxDynamicSharedMemorySize,
                         GEMM_SMEM);
    cudaFuncSetAttribute(attn_tc_kernel, cudaFuncAttributeMaxDynamicSharedMemorySize,
                         ATTN_SMEM);

    rope_tables_kernel<<<(SEQ * 128 + 255) / 256, 256>>>();

    // splits / transposes of inputs (Q/K permuted for RoPE-fused epilogue)
    split_kernel<<<(MROWS * EMBED / 4 + 255) / 256, 256>>>(hid, Hh, Hl, MROWS * EMBED / 4);
    tsplit_kernel<<<dim3(QCOLS / 32, EMBED / 32), dim3(32, 8)>>>(Wq, WpH, WpL, EMBED, QCOLS, 1, 0);
    tsplit_kernel<<<dim3(KCOLS / 32, EMBED / 32), dim3(32, 8)>>>(Wk, WpH, WpL, EMBED, KCOLS, 1, QCOLS);
    tsplit_kernel<<<dim3(KCOLS / 32, EMBED / 32), dim3(32, 8)>>>(Wv, WpH, WpL, EMBED, KCOLS, 0, QCOLS + KCOLS);
    tsplit_kernel<<<dim3(EMBED / 32, QCOLS / 32), dim3(32, 8)>>>(Wo, WotH, WotL, QCOLS, EMBED, 0, 0);

    // fused QKV projection: RoPE+split epilogue for Q/K, fp32 for V
    gemm_mma_kernel<<<dim3(NPACK / 128, MROWS / 128), 256, GEMM_SMEM>>>(
        Hh, Hl, WpH, WpL, nullptr, MROWS, NPACK, EMBED,
        1, Qh, Ql, Kh, Kl, Vb);

    // V transpose+split
    vtsplit_kernel<<<dim3(SEQ / 32, KCOLS / 32, BATCH), dim3(32, 8)>>>(Vb, VtH, VtL);

    // tensor-core attention -> Ch/Cl bf16 splits
    attn_tc_kernel<<<dim3(SEQ / 64, BATCH * NH), 256, ATTN_SMEM>>>(
        Qh, Ql, Kh, Kl, VtH, VtL, Ch, Cl);

    // output projection straight into d_out
    gemm_mma_kernel<<<dim3(EMBED / 128, MROWS / 128), 256, GEMM_SMEM>>>(
        Ch, Cl, WotH, WotL, out, MROWS, EMBED, QCOLS,
        0, nullptr, nullptr, nullptr, nullptr, nullptr);
}